// round 3
// baseline (speedup 1.0000x reference)
#include <cuda_runtime.h>
#include <math.h>

#define NB 16
#define HB 200
#define EMBD 64
#define H1D 128
#define H2D 64
#define PP 19900                 // H*(H-1)/2
#define ROWS (NB*HB)             // 3200
#define TOTPAIRS (NB*PP)         // 318400
#define W1COLS 134               // 2*EMB + 6

// scratch (device globals; no allocation allowed)
__device__ float g_A[ROWS*H1D];      // e_i @ W1a^T
__device__ float g_B[ROWS*H1D];      // e_j @ W1b^T
__device__ float g_catb[6*H1D];      // W1c[:,cat] + b1
__device__ float g_sim[TOTPAIRS];
__device__ float g_vt[ROWS];
__device__ float g_vc[ROWS];

// ---------------------------------------------------------------------------
// Kernel A: per-position projections A,B and category bias table
// grid = ROWS blocks, 128 threads
// ---------------------------------------------------------------------------
__global__ void prep_kernel(const int* __restrict__ skills,
                            const float* __restrict__ emb,
                            const float* __restrict__ W1,
                            const float* __restrict__ b1) {
    int r = blockIdx.x, c = threadIdx.x;
    __shared__ float e[EMBD];
    if (c < EMBD) e[c] = emb[skills[r]*EMBD + c];
    __syncthreads();
    const float* w = W1 + c*W1COLS;
    float a = 0.f, b = 0.f;
#pragma unroll
    for (int k = 0; k < EMBD; k++) {
        a = fmaf(e[k], w[k],        a);
        b = fmaf(e[k], w[EMBD + k], b);
    }
    g_A[r*H1D + c] = a;
    g_B[r*H1D + c] = b;
    if (r < 6)  // reuse first 6 blocks to build cat bias table
        g_catb[r*H1D + c] = W1[c*W1COLS + 2*EMBD + r] + b1[c];
}

// ---------------------------------------------------------------------------
// Kernel B: pairwise MLP (layer1 as adds, layer2 128->64 GEMV, layer3 64->1)
// 128 threads (4 warps); each warp does 4 pairs per pass.
// ---------------------------------------------------------------------------
#define BWARPS 4
__global__ void pair_kernel(const int* __restrict__ skills,
                            const float* __restrict__ ts,
                            const float* __restrict__ W2,
                            const float* __restrict__ b2,
                            const float* __restrict__ W3,
                            const float* __restrict__ b3) {
    __shared__ __align__(16) float W2Ts[H1D*H2D];       // [k][o] 32KB
    __shared__ __align__(16) float h1s[BWARPS][4][H1D]; // 8KB
    __shared__ float catbs[6*H1D];
    __shared__ float b2s[H2D], W3s[H2D];
    __shared__ float b3s;

    int tid = threadIdx.x;
    for (int idx = tid; idx < H1D*H2D; idx += blockDim.x) {
        int k = idx >> 6, o = idx & 63;
        W2Ts[idx] = W2[o*H1D + k];
    }
    for (int idx = tid; idx < 6*H1D; idx += blockDim.x) catbs[idx] = g_catb[idx];
    if (tid < H2D) { b2s[tid] = b2[tid]; W3s[tid] = W3[tid]; }
    if (tid == 0) b3s = b3[0];
    __syncthreads();

    int wid = tid >> 5, lane = tid & 31;
    const int totalChunks = TOTPAIRS / 4;   // 79600; PP%4==0 so chunk never crosses n

    for (int chunk = blockIdx.x*BWARPS + wid; chunk < totalChunks;
         chunk += gridDim.x*BWARPS) {
        int q0 = chunk * 4;
        int n  = q0 / PP;
        int p  = q0 - n*PP;
        // recover (i,j) for first pair of chunk
        int i = (int)((1.0f + sqrtf(1.0f + 8.0f*(float)p)) * 0.5f);
        while (i*(i-1)/2 > p)     --i;
        while ((i+1)*i/2 <= p)    ++i;
        int j = p - i*(i-1)/2;
        int baseRow = n * HB;

#pragma unroll
        for (int u = 0; u < 4; u++) {
            int ri = baseRow + i, rj = baseRow + j;
            float dt = ts[ri] - ts[rj];
            int cat = 1 + (dt > 1.f) + (dt > 3600.f) + (dt > 86400.f) + (dt > 604800.f);
            if (skills[ri] == 0 || skills[rj] == 0) cat = 0;
            const float* Ap = g_A + ri*H1D;
            const float* Bp = g_B + rj*H1D;
            const float* cb = catbs + cat*H1D;
#pragma unroll
            for (int rr = 0; rr < 4; rr++) {
                int c = lane + 32*rr;
                h1s[wid][u][c] = fmaxf(Ap[c] + Bp[c] + cb[c], 0.f);
            }
            // advance pair
            j++; if (j == i) { i++; j = 0; }
        }
        __syncwarp();

        float acc[4][2] = {{0.f,0.f},{0.f,0.f},{0.f,0.f},{0.f,0.f}};
#pragma unroll 4
        for (int k = 0; k < H1D; k += 2) {
            float2 w0 = *(const float2*)&W2Ts[ k   *H2D + 2*lane];
            float2 w1 = *(const float2*)&W2Ts[(k+1)*H2D + 2*lane];
#pragma unroll
            for (int u = 0; u < 4; u++) {
                float2 hv = *(const float2*)&h1s[wid][u][k];
                acc[u][0] = fmaf(hv.x, w0.x, acc[u][0]);
                acc[u][0] = fmaf(hv.y, w1.x, acc[u][0]);
                acc[u][1] = fmaf(hv.x, w0.y, acc[u][1]);
                acc[u][1] = fmaf(hv.y, w1.y, acc[u][1]);
            }
        }
        __syncwarp();

        float b2a = b2s[2*lane], b2b = b2s[2*lane+1];
        float w3a = W3s[2*lane], w3b = W3s[2*lane+1];
        float out4[4];
#pragma unroll
        for (int u = 0; u < 4; u++) {
            float h2a = fmaxf(acc[u][0] + b2a, 0.f);
            float h2b = fmaxf(acc[u][1] + b2b, 0.f);
            float part = fmaf(h2a, w3a, h2b*w3b);
#pragma unroll
            for (int s = 16; s > 0; s >>= 1)
                part += __shfl_xor_sync(0xffffffffu, part, s);
            out4[u] = part;
        }
        if (lane == 0) {
#pragma unroll
            for (int u = 0; u < 4; u++)
                g_sim[q0 + u] = tanhf(out4[u] + b3s);
        }
    }
}

// ---------------------------------------------------------------------------
// Kernel C: segment sums over pairs grouped by i  (warp per (n,i))
// ---------------------------------------------------------------------------
__global__ void seg_kernel(const int* __restrict__ skills,
                           const float* __restrict__ targets) {
    int r    = (blockIdx.x*blockDim.x + threadIdx.x) >> 5;
    int lane = threadIdx.x & 31;
    if (r >= ROWS) return;
    int n = r / HB, i = r % HB;
    const float* sp = g_sim + n*PP + i*(i-1)/2;
    float s = 0.f;
    for (int k = lane; k < i; k += 32) s += sp[k];
#pragma unroll
    for (int sh = 16; sh > 0; sh >>= 1) s += __shfl_xor_sync(0xffffffffu, s, sh);
    if (lane == 0) {
        float vt = (skills[r] != 0) ? s : 0.f;
        g_vt[r] = vt;
        g_vc[r] = vt * targets[r];   // targets[:,pi] constant within segment
    }
}

// ---------------------------------------------------------------------------
// Kernel D: sparse final linear + BCE + sigmoid   (warp per row)
// out layout: [0:3200) loss, [3200:6400) sigmoid(pred), [6400:9600) labels
// ---------------------------------------------------------------------------
__global__ void final_kernel(const float* __restrict__ users,
                             const float* __restrict__ items,
                             const float* __restrict__ langs,
                             const int* __restrict__ skills,
                             const float* __restrict__ targets,
                             const int* __restrict__ mask,   // bool input materialized as int32
                             const float* __restrict__ linW,
                             const float* __restrict__ linb,
                             float* __restrict__ out) {
    int r    = (blockIdx.x*blockDim.x + threadIdx.x) >> 5;
    int lane = threadIdx.x & 31;
    if (r >= ROWS) return;
    int n = r / HB;
    float acc = 0.f;
    const float* u = users + n*100;
    for (int k = lane; k < 100; k += 32) acc = fmaf(u[k], linW[k], acc);
    const float* it = items + r*100;
    for (int k = lane; k < 100; k += 32) acc = fmaf(it[k], linW[100+k], acc);
    if (lane < 10) acc = fmaf(langs[r*10 + lane], linW[200 + lane], acc);
#pragma unroll
    for (int sh = 16; sh > 0; sh >>= 1) acc += __shfl_xor_sync(0xffffffffu, acc, sh);
    if (lane == 0) {
        int s = skills[r];
        float logit = acc + linW[210 + s]
                    + g_vt[r]*linW[2210 + s]
                    + g_vc[r]*linW[4210 + s]
                    + linb[0];
        float label = targets[r];
        float maskf = (mask[r] != 0) ? 1.f : 0.f;
        float bce   = fmaxf(logit, 0.f) - logit*label + log1pf(expf(-fabsf(logit)));
        out[r]          = bce * maskf;
        out[ROWS + r]   = 1.f / (1.f + expf(-logit));
        out[2*ROWS + r] = label;
    }
}

// ---------------------------------------------------------------------------
extern "C" void kernel_launch(void* const* d_in, const int* in_sizes, int n_in,
                              void* d_out, int out_size) {
    const float* users    = (const float*)d_in[0];
    const float* items    = (const float*)d_in[1];
    const float* langs    = (const float*)d_in[2];
    const int*   skills   = (const int*)  d_in[3];
    const float* ts       = (const float*)d_in[4];
    const float* targets  = (const float*)d_in[5];
    const int*   mask     = (const int*)  d_in[6];
    const float* emb      = (const float*)d_in[7];
    const float* W1       = (const float*)d_in[8];
    const float* b1       = (const float*)d_in[9];
    const float* W2       = (const float*)d_in[10];
    const float* b2       = (const float*)d_in[11];
    const float* W3       = (const float*)d_in[12];
    const float* b3       = (const float*)d_in[13];
    const float* linW     = (const float*)d_in[14];
    const float* linb     = (const float*)d_in[15];
    float* out = (float*)d_out;

    prep_kernel<<<ROWS, H1D>>>(skills, emb, W1, b1);
    pair_kernel<<<608, 128>>>(skills, ts, W2, b2, W3, b3);
    seg_kernel<<<(ROWS*32 + 255)/256, 256>>>(skills, targets);
    final_kernel<<<(ROWS*32 + 255)/256, 256>>>(users, items, langs, skills,
                                               targets, mask, linW, linb, out);
}

// round 5
// speedup vs baseline: 2.0101x; 2.0101x over previous
#include <cuda_runtime.h>
#include <math.h>

#define NB 16
#define HB 200
#define EMBD 64
#define H1D 128
#define H2D 64
#define PP 19900                 // H*(H-1)/2
#define ROWS (NB*HB)             // 3200
#define TOTPAIRS (NB*PP)         // 318400
#define W1COLS 134               // 2*EMB + 6

#define TPAIR 16                 // pairs per warp-chunk
#define NCHUNKS (TOTPAIRS/TPAIR) // 19900
#define PWARPS 6                 // warps per pair block
#define PBLOCK (PWARPS*32)       // 192
#define HPAD 20                  // h1t row stride in floats (16 u + 4 pad, 16B aligned)

// scratch (device globals; no allocation allowed)
__device__ float g_A[ROWS*H1D];      // e_i @ W1a^T
__device__ float g_B[ROWS*H1D];      // e_j @ W1b^T
__device__ float g_catb[6*H1D];      // W1c[:,cat] + b1
__device__ float g_sim[TOTPAIRS];
__device__ float g_vt[ROWS];
__device__ float g_vc[ROWS];

// packed f32x2 helpers (Blackwell): 2 fp32 FMAs per instruction
#define FMA2(acc, a, b) \
    asm("fma.rn.f32x2 %0, %1, %2, %0;" : "+l"(acc) : "l"(a), "l"(b))
#define PACK2(d, x) \
    asm("mov.b64 %0, {%1, %1};" : "=l"(d) : "r"(x))
#define UNPACK2(lo, hi, v) \
    asm("mov.b64 {%0, %1}, %2;" : "=r"(lo), "=r"(hi) : "l"(v))

// ---------------------------------------------------------------------------
// Kernel A: per-position projections A,B and category bias table
// ---------------------------------------------------------------------------
__global__ void prep_kernel(const int* __restrict__ skills,
                            const float* __restrict__ emb,
                            const float* __restrict__ W1,
                            const float* __restrict__ b1) {
    int r = blockIdx.x, c = threadIdx.x;
    __shared__ float e[EMBD];
    if (c < EMBD) e[c] = emb[skills[r]*EMBD + c];
    __syncthreads();
    const float* w = W1 + c*W1COLS;
    float a = 0.f, b = 0.f;
#pragma unroll
    for (int k = 0; k < EMBD; k++) {
        a = fmaf(e[k], w[k],        a);
        b = fmaf(e[k], w[EMBD + k], b);
    }
    g_A[r*H1D + c] = a;
    g_B[r*H1D + c] = b;
    if (r < 6)
        g_catb[r*H1D + c] = W1[c*W1COLS + 2*EMBD + r] + b1[c];
}

// ---------------------------------------------------------------------------
// Kernel B: pairwise MLP with packed f32x2 layer-2 GEMV.
// Each warp processes TPAIR=16 pairs per chunk:
//   phase 1: h1[u][k] = relu(A[ri]+B[rj]+catb[cat]) stored k-major (h1t[k][u])
//   phase 2: layer2 128->64 with fma.rn.f32x2 (pack over pair-pairs),
//            epilogue relu+W3 dot+warp reduce+tanh.
// Dynamic smem: W2Ts[128][64] | h1t[PWARPS][128][HPAD] | catbs[6][128] | b2,W3,b3
// ---------------------------------------------------------------------------
__global__ void __launch_bounds__(PBLOCK, 2)
pair_kernel(const int* __restrict__ skills,
            const float* __restrict__ ts,
            const float* __restrict__ W2,
            const float* __restrict__ b2,
            const float* __restrict__ W3,
            const float* __restrict__ b3) {
    extern __shared__ float smem[];
    float* W2Ts  = smem;                         // 8192 floats, [k][o]
    float* h1t   = W2Ts + H1D*H2D;               // PWARPS*128*HPAD
    float* catbs = h1t + PWARPS*H1D*HPAD;        // 768
    float* b2s   = catbs + 6*H1D;                // 64
    float* W3s   = b2s + H2D;                    // 64
    float* b3p   = W3s + H2D;                    // 1

    int tid = threadIdx.x;
    for (int idx = tid; idx < H1D*H2D; idx += PBLOCK) {
        int k = idx >> 6, o = idx & 63;
        W2Ts[idx] = W2[o*H1D + k];
    }
    for (int idx = tid; idx < 6*H1D; idx += PBLOCK) catbs[idx] = g_catb[idx];
    if (tid < H2D) { b2s[tid] = b2[tid]; W3s[tid] = W3[tid]; }
    if (tid == 0) b3p[0] = b3[0];
    __syncthreads();

    int wid = tid >> 5, lane = tid & 31;
    float* h1w = h1t + wid * (H1D*HPAD);

    float2 b2v = *(const float2*)&b2s[2*lane];
    float2 w3v = *(const float2*)&W3s[2*lane];
    float  b3s = b3p[0];

    for (int chunk = blockIdx.x*PWARPS + wid; chunk < NCHUNKS;
         chunk += gridDim.x*PWARPS) {
        int q0 = chunk * TPAIR;
        int n  = q0 / PP;
        int p  = q0 - n*PP;
        int i = (int)((1.0f + sqrtf(1.0f + 8.0f*(float)p)) * 0.5f);
        while (i*(i-1)/2 > p)  --i;
        while ((i+1)*i/2 <= p) ++i;
        int j = p - i*(i-1)/2;

        // ---- phase 1: build h1t[k][u] (k-major, transposed) ----
#pragma unroll
        for (int u = 0; u < TPAIR; u++) {
            int ri = n*HB + i, rj = n*HB + j;
            float dt = ts[ri] - ts[rj];
            int cat = 1 + (dt > 1.f) + (dt > 3600.f) + (dt > 86400.f) + (dt > 604800.f);
            if (skills[ri] == 0 || skills[rj] == 0) cat = 0;
            const float* Ap = g_A + ri*H1D;
            const float* Bp = g_B + rj*H1D;
            const float* cb = catbs + cat*H1D;
#pragma unroll
            for (int rr = 0; rr < 4; rr++) {
                int c = lane + 32*rr;
                h1w[c*HPAD + u] = fmaxf(Ap[c] + Bp[c] + cb[c], 0.f);
            }
            j++; if (j == i) { i++; j = 0; }
            if (i == HB) { n++; i = 1; j = 0; }
        }
        __syncwarp();

        // ---- phase 2: layer-2 GEMV, packed over pair-pairs ----
        // acc[o_local][up]: o = 2*lane + o_local; up covers pairs (2up, 2up+1)
        unsigned long long acc[2][8];
#pragma unroll
        for (int a = 0; a < 2; a++)
#pragma unroll
            for (int u = 0; u < 8; u++) acc[a][u] = 0ull;

#pragma unroll 4
        for (int k = 0; k < H1D; k++) {
            float2 wv = *(const float2*)&W2Ts[k*H2D + 2*lane];
            unsigned long long wx, wy;
            PACK2(wx, __float_as_uint(wv.x));
            PACK2(wy, __float_as_uint(wv.y));
            const ulonglong2* hp = (const ulonglong2*)(h1w + k*HPAD);
#pragma unroll
            for (int b = 0; b < 4; b++) {
                ulonglong2 hv = hp[b];   // pairs (4b,4b+1) and (4b+2,4b+3)
                FMA2(acc[0][2*b],   hv.x, wx);
                FMA2(acc[1][2*b],   hv.x, wy);
                FMA2(acc[0][2*b+1], hv.y, wx);
                FMA2(acc[1][2*b+1], hv.y, wy);
            }
        }

        // ---- epilogue: relu + W3 dot + warp reduce + tanh ----
#pragma unroll
        for (int up = 0; up < 8; up++) {
            unsigned int l0, h0, l1, h1;
            UNPACK2(l0, h0, acc[0][up]);
            UNPACK2(l1, h1, acc[1][up]);
            float pa = fmaf(fmaxf(__uint_as_float(l0) + b2v.x, 0.f), w3v.x,
                            fmaxf(__uint_as_float(l1) + b2v.y, 0.f) * w3v.y);
            float pb = fmaf(fmaxf(__uint_as_float(h0) + b2v.x, 0.f), w3v.x,
                            fmaxf(__uint_as_float(h1) + b2v.y, 0.f) * w3v.y);
#pragma unroll
            for (int s = 16; s > 0; s >>= 1) {
                pa += __shfl_xor_sync(0xffffffffu, pa, s);
                pb += __shfl_xor_sync(0xffffffffu, pb, s);
            }
            if (lane == 2*up)     g_sim[q0 + 2*up]     = tanhf(pa + b3s);
            if (lane == 2*up + 1) g_sim[q0 + 2*up + 1] = tanhf(pb + b3s);
        }
        __syncwarp();
    }
}

// ---------------------------------------------------------------------------
// Kernel C: segment sums over pairs grouped by i  (warp per (n,i))
// ---------------------------------------------------------------------------
__global__ void seg_kernel(const int* __restrict__ skills,
                           const float* __restrict__ targets) {
    int r    = (blockIdx.x*blockDim.x + threadIdx.x) >> 5;
    int lane = threadIdx.x & 31;
    if (r >= ROWS) return;
    int n = r / HB, i = r % HB;
    const float* sp = g_sim + n*PP + i*(i-1)/2;
    float s = 0.f;
    for (int k = lane; k < i; k += 32) s += sp[k];
#pragma unroll
    for (int sh = 16; sh > 0; sh >>= 1) s += __shfl_xor_sync(0xffffffffu, s, sh);
    if (lane == 0) {
        float vt = (skills[r] != 0) ? s : 0.f;
        g_vt[r] = vt;
        g_vc[r] = vt * targets[r];
    }
}

// ---------------------------------------------------------------------------
// Kernel D: sparse final linear + BCE + sigmoid   (warp per row)
// ---------------------------------------------------------------------------
__global__ void final_kernel(const float* __restrict__ users,
                             const float* __restrict__ items,
                             const float* __restrict__ langs,
                             const int* __restrict__ skills,
                             const float* __restrict__ targets,
                             const int* __restrict__ mask,
                             const float* __restrict__ linW,
                             const float* __restrict__ linb,
                             float* __restrict__ out) {
    int r    = (blockIdx.x*blockDim.x + threadIdx.x) >> 5;
    int lane = threadIdx.x & 31;
    if (r >= ROWS) return;
    int n = r / HB;
    float acc = 0.f;
    const float* u = users + n*100;
    for (int k = lane; k < 100; k += 32) acc = fmaf(u[k], linW[k], acc);
    const float* it = items + r*100;
    for (int k = lane; k < 100; k += 32) acc = fmaf(it[k], linW[100+k], acc);
    if (lane < 10) acc = fmaf(langs[r*10 + lane], linW[200 + lane], acc);
#pragma unroll
    for (int sh = 16; sh > 0; sh >>= 1) acc += __shfl_xor_sync(0xffffffffu, acc, sh);
    if (lane == 0) {
        int s = skills[r];
        float logit = acc + linW[210 + s]
                    + g_vt[r]*linW[2210 + s]
                    + g_vc[r]*linW[4210 + s]
                    + linb[0];
        float label = targets[r];
        float maskf = (mask[r] != 0) ? 1.f : 0.f;
        float bce   = fmaxf(logit, 0.f) - logit*label + log1pf(expf(-fabsf(logit)));
        out[r]          = bce * maskf;
        out[ROWS + r]   = 1.f / (1.f + expf(-logit));
        out[2*ROWS + r] = label;
    }
}

// ---------------------------------------------------------------------------
extern "C" void kernel_launch(void* const* d_in, const int* in_sizes, int n_in,
                              void* d_out, int out_size) {
    const float* users    = (const float*)d_in[0];
    const float* items    = (const float*)d_in[1];
    const float* langs    = (const float*)d_in[2];
    const int*   skills   = (const int*)  d_in[3];
    const float* ts       = (const float*)d_in[4];
    const float* targets  = (const float*)d_in[5];
    const int*   mask     = (const int*)  d_in[6];
    const float* emb      = (const float*)d_in[7];
    const float* W1       = (const float*)d_in[8];
    const float* b1       = (const float*)d_in[9];
    const float* W2       = (const float*)d_in[10];
    const float* b2       = (const float*)d_in[11];
    const float* W3       = (const float*)d_in[12];
    const float* b3       = (const float*)d_in[13];
    const float* linW     = (const float*)d_in[14];
    const float* linb     = (const float*)d_in[15];
    float* out = (float*)d_out;

    // dynamic smem for pair_kernel
    int smemFloats = H1D*H2D + PWARPS*H1D*HPAD + 6*H1D + 2*H2D + 1;
    size_t smemBytes = (size_t)smemFloats * sizeof(float);
    static int configured = -1;
    if (configured < 0) {
        cudaFuncSetAttribute(pair_kernel,
                             cudaFuncAttributeMaxDynamicSharedMemorySize,
                             (int)smemBytes);
        configured = 1;
    }

    prep_kernel<<<ROWS, H1D>>>(skills, emb, W1, b1);
    pair_kernel<<<304, PBLOCK, smemBytes>>>(skills, ts, W2, b2, W3, b3);
    seg_kernel<<<(ROWS*32 + 255)/256, 256>>>(skills, targets);
    final_kernel<<<(ROWS*32 + 255)/256, 256>>>(users, items, langs, skills,
                                               targets, mask, linW, linb, out);
}

// round 6
// speedup vs baseline: 2.2937x; 1.1411x over previous
#include <cuda_runtime.h>
#include <math.h>

#define NB 16
#define HB 200
#define EMBD 64
#define H1D 128
#define H2D 64
#define PP 19900                 // H*(H-1)/2
#define ROWS (NB*HB)             // 3200
#define TOTPAIRS (NB*PP)         // 318400
#define W1COLS 134               // 2*EMB + 6

#define TPAIR 16                 // pairs per warp-chunk
#define NCHUNKS (TOTPAIRS/TPAIR) // 19900
#define PWARPS 6                 // warps per pair block
#define PBLOCK (PWARPS*32)       // 192
#define HPAD 20                  // h1t row stride in floats

#define RPB 20                   // rows per prep block (3200/160)
#define PREPBLK 160

// scratch (device globals; no allocation allowed)
__device__ float g_A[ROWS*H1D];      // e_i @ W1a^T
__device__ float g_B[ROWS*H1D];      // e_j @ W1b^T
__device__ float g_catb[6*H1D];      // W1c[:,cat] + b1
__device__ float g_sim[TOTPAIRS];
__device__ float g_vt[ROWS];
__device__ float g_vc[ROWS];

// packed f32x2 helpers (Blackwell): 2 fp32 FMAs per instruction
#define FMA2(acc, a, b) \
    asm("fma.rn.f32x2 %0, %1, %2, %0;" : "+l"(acc) : "l"(a), "l"(b))
#define PACK2(d, x) \
    asm("mov.b64 %0, {%1, %1};" : "=l"(d) : "r"(x))
#define UNPACK2(lo, hi, v) \
    asm("mov.b64 {%0, %1}, %2;" : "=r"(lo), "=r"(hi) : "l"(v))

// ---------------------------------------------------------------------------
// Kernel A (rewritten): coalesced, smem-tiled per-position projections.
// 160 blocks x 256 threads; each block: stage W1a^T/W1b^T (k-major) + 20
// embedding rows in smem, compute A/B for its 20 rows.
// Dyn smem: W1aT[64*128] | W1bT[64*128] | es[RPB*64]
// ---------------------------------------------------------------------------
__global__ void __launch_bounds__(256, 1)
prep_kernel(const int* __restrict__ skills,
            const float* __restrict__ emb,
            const float* __restrict__ W1,
            const float* __restrict__ b1) {
    extern __shared__ float psm[];
    float* W1aT = psm;                 // [k][c] 64x128
    float* W1bT = W1aT + EMBD*H1D;     // [k][c] 64x128
    float* es   = W1bT + EMBD*H1D;     // [row][k] RPB x 64
    __shared__ int sk[RPB];

    int tid = threadIdx.x;
    int r0  = blockIdx.x * RPB;

    // stage W1 (coalesced linear read; scatter into k-major smem)
    for (int idx = tid; idx < H1D*W1COLS; idx += 256) {
        int c = idx / W1COLS, j = idx - c*W1COLS;
        float v = W1[idx];
        if (j < EMBD)            W1aT[j*H1D + c] = v;
        else if (j < 2*EMBD)     W1bT[(j-EMBD)*H1D + c] = v;
        else if (blockIdx.x == 0) g_catb[(j-2*EMBD)*H1D + c] = v + b1[c];
    }
    if (tid < RPB) sk[tid] = skills[r0 + tid];
    __syncthreads();
    // stage embedding rows (coalesced within each 64-float row)
    for (int idx = tid; idx < RPB*EMBD; idx += 256) {
        int row = idx >> 6, k = idx & 63;
        es[row*EMBD + k] = emb[sk[row]*EMBD + k];
    }
    __syncthreads();

    int rowh = tid >> 7;       // 0 or 1
    int c    = tid & 127;
    for (int rp = 0; rp < RPB; rp += 2) {
        int row = rp + rowh;
        const float* e = es + row*EMBD;
        float a = 0.f, b = 0.f;
#pragma unroll
        for (int k = 0; k < EMBD; k++) {
            float ev = e[k];
            a = fmaf(ev, W1aT[k*H1D + c], a);
            b = fmaf(ev, W1bT[k*H1D + c], b);
        }
        g_A[(r0+row)*H1D + c] = a;
        g_B[(r0+row)*H1D + c] = b;
    }
}

// ---------------------------------------------------------------------------
// Kernel B: pairwise MLP with packed f32x2 layer-2 GEMV. (unchanged)
// ---------------------------------------------------------------------------
__global__ void __launch_bounds__(PBLOCK, 2)
pair_kernel(const int* __restrict__ skills,
            const float* __restrict__ ts,
            const float* __restrict__ W2,
            const float* __restrict__ b2,
            const float* __restrict__ W3,
            const float* __restrict__ b3) {
    extern __shared__ float smem[];
    float* W2Ts  = smem;                         // 8192 floats, [k][o]
    float* h1t   = W2Ts + H1D*H2D;               // PWARPS*128*HPAD
    float* catbs = h1t + PWARPS*H1D*HPAD;        // 768
    float* b2s   = catbs + 6*H1D;                // 64
    float* W3s   = b2s + H2D;                    // 64
    float* b3p   = W3s + H2D;                    // 1

    int tid = threadIdx.x;
    for (int idx = tid; idx < H1D*H2D; idx += PBLOCK) {
        int k = idx >> 6, o = idx & 63;
        W2Ts[idx] = W2[o*H1D + k];
    }
    for (int idx = tid; idx < 6*H1D; idx += PBLOCK) catbs[idx] = g_catb[idx];
    if (tid < H2D) { b2s[tid] = b2[tid]; W3s[tid] = W3[tid]; }
    if (tid == 0) b3p[0] = b3[0];
    __syncthreads();

    int wid = tid >> 5, lane = tid & 31;
    float* h1w = h1t + wid * (H1D*HPAD);

    float2 b2v = *(const float2*)&b2s[2*lane];
    float2 w3v = *(const float2*)&W3s[2*lane];
    float  b3s = b3p[0];

    for (int chunk = blockIdx.x*PWARPS + wid; chunk < NCHUNKS;
         chunk += gridDim.x*PWARPS) {
        int q0 = chunk * TPAIR;
        int n  = q0 / PP;
        int p  = q0 - n*PP;
        int i = (int)((1.0f + sqrtf(1.0f + 8.0f*(float)p)) * 0.5f);
        while (i*(i-1)/2 > p)  --i;
        while ((i+1)*i/2 <= p) ++i;
        int j = p - i*(i-1)/2;

        // ---- phase 1: build h1t[k][u] (k-major, transposed) ----
#pragma unroll
        for (int u = 0; u < TPAIR; u++) {
            int ri = n*HB + i, rj = n*HB + j;
            float dt = ts[ri] - ts[rj];
            int cat = 1 + (dt > 1.f) + (dt > 3600.f) + (dt > 86400.f) + (dt > 604800.f);
            if (skills[ri] == 0 || skills[rj] == 0) cat = 0;
            const float* Ap = g_A + ri*H1D;
            const float* Bp = g_B + rj*H1D;
            const float* cb = catbs + cat*H1D;
#pragma unroll
            for (int rr = 0; rr < 4; rr++) {
                int c = lane + 32*rr;
                h1w[c*HPAD + u] = fmaxf(Ap[c] + Bp[c] + cb[c], 0.f);
            }
            j++; if (j == i) { i++; j = 0; }
            if (i == HB) { n++; i = 1; j = 0; }
        }
        __syncwarp();

        // ---- phase 2: layer-2 GEMV, packed over pair-pairs ----
        unsigned long long acc[2][8];
#pragma unroll
        for (int a = 0; a < 2; a++)
#pragma unroll
            for (int u = 0; u < 8; u++) acc[a][u] = 0ull;

#pragma unroll 4
        for (int k = 0; k < H1D; k++) {
            float2 wv = *(const float2*)&W2Ts[k*H2D + 2*lane];
            unsigned long long wx, wy;
            PACK2(wx, __float_as_uint(wv.x));
            PACK2(wy, __float_as_uint(wv.y));
            const ulonglong2* hp = (const ulonglong2*)(h1w + k*HPAD);
#pragma unroll
            for (int b = 0; b < 4; b++) {
                ulonglong2 hv = hp[b];
                FMA2(acc[0][2*b],   hv.x, wx);
                FMA2(acc[1][2*b],   hv.x, wy);
                FMA2(acc[0][2*b+1], hv.y, wx);
                FMA2(acc[1][2*b+1], hv.y, wy);
            }
        }

        // ---- epilogue: relu + W3 dot + warp reduce + tanh ----
#pragma unroll
        for (int up = 0; up < 8; up++) {
            unsigned int l0, h0, l1, h1;
            UNPACK2(l0, h0, acc[0][up]);
            UNPACK2(l1, h1, acc[1][up]);
            float pa = fmaf(fmaxf(__uint_as_float(l0) + b2v.x, 0.f), w3v.x,
                            fmaxf(__uint_as_float(l1) + b2v.y, 0.f) * w3v.y);
            float pb = fmaf(fmaxf(__uint_as_float(h0) + b2v.x, 0.f), w3v.x,
                            fmaxf(__uint_as_float(h1) + b2v.y, 0.f) * w3v.y);
#pragma unroll
            for (int s = 16; s > 0; s >>= 1) {
                pa += __shfl_xor_sync(0xffffffffu, pa, s);
                pb += __shfl_xor_sync(0xffffffffu, pb, s);
            }
            if (lane == 2*up)     g_sim[q0 + 2*up]     = tanhf(pa + b3s);
            if (lane == 2*up + 1) g_sim[q0 + 2*up + 1] = tanhf(pb + b3s);
        }
        __syncwarp();
    }
}

// ---------------------------------------------------------------------------
// Kernel C: segment sums over pairs grouped by i  (warp per (n,i))
// ---------------------------------------------------------------------------
__global__ void seg_kernel(const int* __restrict__ skills,
                           const float* __restrict__ targets) {
    int r    = (blockIdx.x*blockDim.x + threadIdx.x) >> 5;
    int lane = threadIdx.x & 31;
    if (r >= ROWS) return;
    int n = r / HB, i = r % HB;
    const float* sp = g_sim + n*PP + i*(i-1)/2;
    float s = 0.f;
    for (int k = lane; k < i; k += 32) s += sp[k];
#pragma unroll
    for (int sh = 16; sh > 0; sh >>= 1) s += __shfl_xor_sync(0xffffffffu, s, sh);
    if (lane == 0) {
        float vt = (skills[r] != 0) ? s : 0.f;
        g_vt[r] = vt;
        g_vc[r] = vt * targets[r];
    }
}

// ---------------------------------------------------------------------------
// Kernel D: sparse final linear + BCE + sigmoid   (warp per row)
// ---------------------------------------------------------------------------
__global__ void final_kernel(const float* __restrict__ users,
                             const float* __restrict__ items,
                             const float* __restrict__ langs,
                             const int* __restrict__ skills,
                             const float* __restrict__ targets,
                             const int* __restrict__ mask,
                             const float* __restrict__ linW,
                             const float* __restrict__ linb,
                             float* __restrict__ out) {
    int r    = (blockIdx.x*blockDim.x + threadIdx.x) >> 5;
    int lane = threadIdx.x & 31;
    if (r >= ROWS) return;
    int n = r / HB;
    float acc = 0.f;
    const float* u = users + n*100;
    for (int k = lane; k < 100; k += 32) acc = fmaf(u[k], linW[k], acc);
    const float* it = items + r*100;
    for (int k = lane; k < 100; k += 32) acc = fmaf(it[k], linW[100+k], acc);
    if (lane < 10) acc = fmaf(langs[r*10 + lane], linW[200 + lane], acc);
#pragma unroll
    for (int sh = 16; sh > 0; sh >>= 1) acc += __shfl_xor_sync(0xffffffffu, acc, sh);
    if (lane == 0) {
        int s = skills[r];
        float logit = acc + linW[210 + s]
                    + g_vt[r]*linW[2210 + s]
                    + g_vc[r]*linW[4210 + s]
                    + linb[0];
        float label = targets[r];
        float maskf = (mask[r] != 0) ? 1.f : 0.f;
        float bce   = fmaxf(logit, 0.f) - logit*label + log1pf(expf(-fabsf(logit)));
        out[r]          = bce * maskf;
        out[ROWS + r]   = 1.f / (1.f + expf(-logit));
        out[2*ROWS + r] = label;
    }
}

// ---------------------------------------------------------------------------
extern "C" void kernel_launch(void* const* d_in, const int* in_sizes, int n_in,
                              void* d_out, int out_size) {
    const float* users    = (const float*)d_in[0];
    const float* items    = (const float*)d_in[1];
    const float* langs    = (const float*)d_in[2];
    const int*   skills   = (const int*)  d_in[3];
    const float* ts       = (const float*)d_in[4];
    const float* targets  = (const float*)d_in[5];
    const int*   mask     = (const int*)  d_in[6];
    const float* emb      = (const float*)d_in[7];
    const float* W1       = (const float*)d_in[8];
    const float* b1       = (const float*)d_in[9];
    const float* W2       = (const float*)d_in[10];
    const float* b2       = (const float*)d_in[11];
    const float* W3       = (const float*)d_in[12];
    const float* b3       = (const float*)d_in[13];
    const float* linW     = (const float*)d_in[14];
    const float* linb     = (const float*)d_in[15];
    float* out = (float*)d_out;

    int pairFloats = H1D*H2D + PWARPS*H1D*HPAD + 6*H1D + 2*H2D + 1;
    size_t pairBytes = (size_t)pairFloats * sizeof(float);
    size_t prepBytes = (size_t)(2*EMBD*H1D + RPB*EMBD) * sizeof(float);
    static int configured = -1;
    if (configured < 0) {
        cudaFuncSetAttribute(pair_kernel,
                             cudaFuncAttributeMaxDynamicSharedMemorySize,
                             (int)pairBytes);
        cudaFuncSetAttribute(prep_kernel,
                             cudaFuncAttributeMaxDynamicSharedMemorySize,
                             (int)prepBytes);
        configured = 1;
    }

    prep_kernel<<<PREPBLK, 256, prepBytes>>>(skills, emb, W1, b1);
    pair_kernel<<<304, PBLOCK, pairBytes>>>(skills, ts, W2, b2, W3, b3);
    seg_kernel<<<(ROWS*32 + 255)/256, 256>>>(skills, targets);
    final_kernel<<<(ROWS*32 + 255)/256, 256>>>(users, items, langs, skills,
                                               targets, mask, linW, linb, out);
}

// round 9
// speedup vs baseline: 3.3288x; 1.4513x over previous
#include <cuda_runtime.h>
#include <cuda_bf16.h>
#include <math.h>
#include <stdint.h>

#define NB 16
#define HB 200
#define EMBD 64
#define H1D 128
#define H2D 64
#define PP 19900                 // H*(H-1)/2
#define ROWS (NB*HB)             // 3200
#define TOTPAIRS (NB*PP)         // 318400
#define W1COLS 134               // 2*EMB + 6

#define RPB 20                   // rows per prep block
#define PREPBLK 160

#define NTILES ((TOTPAIRS + 127) / 128)   // 2488
#define TCGRID 304

#define HSTRIDE_B 272            // h row stride in bytes (128 bf16 + 8 pad)
#define A_HI_OFF 0
#define A_LO_OFF 34816           // 128*272
#define RED_OFF  69632           // + 128*272
#define SMEM_DYN (RED_OFF + 8*128*4)   // 73728

// scratch (device globals; no allocation allowed)
__device__ float g_A[ROWS*H1D];      // e_i @ W1a^T
__device__ float g_B[ROWS*H1D];      // e_j @ W1b^T
__device__ float g_catb[6*H1D];      // W1c[:,cat] + b1
__device__ float g_sim[TOTPAIRS];
__device__ float g_vt[ROWS];
__device__ float g_vc[ROWS];

__device__ __forceinline__ uint32_t smem_to_u32(const void* p) {
    uint32_t a;
    asm("{ .reg .u64 t; cvta.to.shared.u64 t, %1; cvt.u32.u64 %0, t; }"
        : "=r"(a) : "l"(p));
    return a;
}

__device__ __forceinline__ void ldmatrix_x4(uint32_t& r0, uint32_t& r1,
                                            uint32_t& r2, uint32_t& r3,
                                            uint32_t addr) {
    asm volatile("ldmatrix.sync.aligned.m8n8.x4.shared.b16 {%0,%1,%2,%3}, [%4];"
                 : "=r"(r0), "=r"(r1), "=r"(r2), "=r"(r3) : "r"(addr));
}

__device__ __forceinline__ void mma_bf16(float& d0, float& d1, float& d2, float& d3,
                                         uint32_t a0, uint32_t a1, uint32_t a2, uint32_t a3,
                                         uint32_t b0, uint32_t b1) {
    asm volatile("mma.sync.aligned.m16n8k16.row.col.f32.bf16.bf16.f32 "
                 "{%0,%1,%2,%3}, {%4,%5,%6,%7}, {%8,%9}, {%0,%1,%2,%3};"
                 : "+f"(d0), "+f"(d1), "+f"(d2), "+f"(d3)
                 : "r"(a0), "r"(a1), "r"(a2), "r"(a3), "r"(b0), "r"(b1));
}

// ---------------------------------------------------------------------------
// Kernel A: coalesced, smem-tiled per-position projections (unchanged)
// ---------------------------------------------------------------------------
__global__ void __launch_bounds__(256, 1)
prep_kernel(const int* __restrict__ skills,
            const float* __restrict__ emb,
            const float* __restrict__ W1,
            const float* __restrict__ b1) {
    extern __shared__ float psm[];
    float* W1aT = psm;
    float* W1bT = W1aT + EMBD*H1D;
    float* es   = W1bT + EMBD*H1D;
    __shared__ int sk[RPB];

    int tid = threadIdx.x;
    int r0  = blockIdx.x * RPB;

    for (int idx = tid; idx < H1D*W1COLS; idx += 256) {
        int c = idx / W1COLS, j = idx - c*W1COLS;
        float v = W1[idx];
        if (j < EMBD)            W1aT[j*H1D + c] = v;
        else if (j < 2*EMBD)     W1bT[(j-EMBD)*H1D + c] = v;
        else if (blockIdx.x == 0) g_catb[(j-2*EMBD)*H1D + c] = v + b1[c];
    }
    if (tid < RPB) sk[tid] = skills[r0 + tid];
    __syncthreads();
    for (int idx = tid; idx < RPB*EMBD; idx += 256) {
        int row = idx >> 6, k = idx & 63;
        es[row*EMBD + k] = emb[sk[row]*EMBD + k];
    }
    __syncthreads();

    int rowh = tid >> 7;
    int c    = tid & 127;
    for (int rp = 0; rp < RPB; rp += 2) {
        int row = rp + rowh;
        const float* e = es + row*EMBD;
        float a = 0.f, b = 0.f;
#pragma unroll
        for (int k = 0; k < EMBD; k++) {
            float ev = e[k];
            a = fmaf(ev, W1aT[k*H1D + c], a);
            b = fmaf(ev, W1bT[k*H1D + c], b);
        }
        g_A[(r0+row)*H1D + c] = a;
        g_B[(r0+row)*H1D + c] = b;
    }
}

// ---------------------------------------------------------------------------
// Kernel B (warp-MMA rewrite): tile = 128 pairs x 64 outputs.
// 8 warps; warp w owns output cols [8w, 8w+8). W2 hi/lo frags in registers.
// Per tile: phase1 h1->smem bf16 hi/lo; 8 mt x 8 kt x 3 mma.sync; epilogue.
// ---------------------------------------------------------------------------
__global__ void __launch_bounds__(256, 2)
pair_tc_kernel(const int* __restrict__ skills,
               const float* __restrict__ ts,
               const float* __restrict__ W2,
               const float* __restrict__ b2,
               const float* __restrict__ W3,
               const float* __restrict__ b3) {
    extern __shared__ __align__(16) char smem[];
    float* red = (float*)(smem + RED_OFF);     // [8][128]

    __shared__ float catbs[6*H1D];
    __shared__ float b2s[H2D], W3s[H2D];
    __shared__ float b3s_sh;

    int tid = threadIdx.x, wid = tid >> 5, lane = tid & 31;
    int g = lane >> 2, t = lane & 3;
    int n0 = wid * 8;

    for (int idx = tid; idx < 6*H1D; idx += 256) catbs[idx] = g_catb[idx];
    if (tid < H2D) { b2s[tid] = b2[tid]; W3s[tid] = W3[tid]; }
    if (tid == 0) b3s_sh = b3[0];

    // ---- build W2 hi/lo B-fragments in registers (col = n0+g, rows = k) ----
    uint32_t bH[8][2], bL[8][2];
    {
        const float* wrow = W2 + (n0 + g) * H1D;
#pragma unroll
        for (int kt = 0; kt < 8; kt++) {
#pragma unroll
            for (int hb = 0; hb < 2; hb++) {
                int k0 = kt*16 + t*2 + hb*8;
                float w0 = wrow[k0], w1 = wrow[k0+1];
                __nv_bfloat16 h0 = __float2bfloat16(w0);
                __nv_bfloat16 h1 = __float2bfloat16(w1);
                __nv_bfloat162 hp; hp.x = h0; hp.y = h1;
                __nv_bfloat162 lp = __floats2bfloat162_rn(w0 - __bfloat162float(h0),
                                                          w1 - __bfloat162float(h1));
                bH[kt][hb] = *reinterpret_cast<uint32_t*>(&hp);
                bL[kt][hb] = *reinterpret_cast<uint32_t*>(&lp);
            }
        }
    }
    __syncthreads();

    uint32_t smem_base = smem_to_u32(smem);
    // epilogue per-lane constants (C cols = n0 + t*2, t*2+1)
    float b2a = b2s[n0 + t*2], b2b = b2s[n0 + t*2 + 1];
    float w3a = W3s[n0 + t*2], w3b = W3s[n0 + t*2 + 1];

    for (int tile = blockIdx.x; tile < NTILES; tile += TCGRID) {
        // ---- phase 1: h1 tile -> smem bf16 hi/lo ----
        {
            int m    = tid & 127;
            int half = tid >> 7;
            int pq = tile*128 + m;
            int q  = (pq < TOTPAIRS) ? pq : (TOTPAIRS - 1);
            int n  = q / PP, p = q - n*PP;
            int i = (int)((1.0f + sqrtf(1.0f + 8.0f*(float)p)) * 0.5f);
            while (i*(i-1)/2 > p)  --i;
            while ((i+1)*i/2 <= p) ++i;
            int j = p - i*(i-1)/2;
            int ri = n*HB + i, rj = n*HB + j;
            float dt = ts[ri] - ts[rj];
            int cat = 1 + (dt > 1.f) + (dt > 3600.f) + (dt > 86400.f) + (dt > 604800.f);
            if (skills[ri] == 0 || skills[rj] == 0) cat = 0;
            const float* Ap = g_A + ri*H1D;
            const float* Bp = g_B + rj*H1D;
            const float* cb = catbs + cat*H1D;
            char* rowHi = smem + A_HI_OFF + m*HSTRIDE_B;
            char* rowLo = smem + A_LO_OFF + m*HSTRIDE_B;
#pragma unroll
            for (int kk = 0; kk < 16; kk++) {
                int c0 = half*64 + kk*4;
                float4 av = *(const float4*)(Ap + c0);
                float4 bv = *(const float4*)(Bp + c0);
                float4 cv = *(const float4*)(cb + c0);
                float h0 = fmaxf(av.x + bv.x + cv.x, 0.f);
                float h1 = fmaxf(av.y + bv.y + cv.y, 0.f);
                float h2 = fmaxf(av.z + bv.z + cv.z, 0.f);
                float h3 = fmaxf(av.w + bv.w + cv.w, 0.f);
                __nv_bfloat162 hp0; hp0.x = __float2bfloat16(h0); hp0.y = __float2bfloat16(h1);
                __nv_bfloat162 hp1; hp1.x = __float2bfloat16(h2); hp1.y = __float2bfloat16(h3);
                float2 f0 = __bfloat1622float2(hp0);
                float2 f1 = __bfloat1622float2(hp1);
                __nv_bfloat162 lp0 = __floats2bfloat162_rn(h0 - f0.x, h1 - f0.y);
                __nv_bfloat162 lp1 = __floats2bfloat162_rn(h2 - f1.x, h3 - f1.y);
                uint2 hv, lv;
                hv.x = *reinterpret_cast<uint32_t*>(&hp0);
                hv.y = *reinterpret_cast<uint32_t*>(&hp1);
                lv.x = *reinterpret_cast<uint32_t*>(&lp0);
                lv.y = *reinterpret_cast<uint32_t*>(&lp1);
                *(uint2*)(rowHi + c0*2) = hv;
                *(uint2*)(rowLo + c0*2) = lv;
            }
        }
        __syncthreads();

        // ---- MMA + per-mt epilogue ----
        {
            uint32_t laddrHi = smem_base + A_HI_OFF
                             + (uint32_t)(lane & 15) * HSTRIDE_B
                             + (uint32_t)(lane >> 4) * 16;
            uint32_t laddrLo = laddrHi + (A_LO_OFF - A_HI_OFF);
#pragma unroll
            for (int mt = 0; mt < 8; mt++) {
                float d0 = 0.f, d1 = 0.f, d2 = 0.f, d3 = 0.f;
                uint32_t mOff = (uint32_t)(mt*16) * HSTRIDE_B;
#pragma unroll
                for (int kt = 0; kt < 8; kt++) {
                    uint32_t aH0,aH1,aH2,aH3, aL0,aL1,aL2,aL3;
                    ldmatrix_x4(aH0,aH1,aH2,aH3, laddrHi + mOff + kt*32);
                    ldmatrix_x4(aL0,aL1,aL2,aL3, laddrLo + mOff + kt*32);
                    mma_bf16(d0,d1,d2,d3, aH0,aH1,aH2,aH3, bH[kt][0], bH[kt][1]);
                    mma_bf16(d0,d1,d2,d3, aL0,aL1,aL2,aL3, bH[kt][0], bH[kt][1]);
                    mma_bf16(d0,d1,d2,d3, aH0,aH1,aH2,aH3, bL[kt][0], bL[kt][1]);
                }
                // epilogue for rows mt*16+g (d0,d1) and mt*16+8+g (d2,d3)
                float p0 = fmaf(fmaxf(d0 + b2a, 0.f), w3a, fmaxf(d1 + b2b, 0.f) * w3b);
                float p1 = fmaf(fmaxf(d2 + b2a, 0.f), w3a, fmaxf(d3 + b2b, 0.f) * w3b);
                p0 += __shfl_xor_sync(0xffffffffu, p0, 1);
                p0 += __shfl_xor_sync(0xffffffffu, p0, 2);
                p1 += __shfl_xor_sync(0xffffffffu, p1, 1);
                p1 += __shfl_xor_sync(0xffffffffu, p1, 2);
                if (t == 0) {
                    red[wid*128 + mt*16 + g]     = p0;
                    red[wid*128 + mt*16 + 8 + g] = p1;
                }
            }
        }
        __syncthreads();

        // ---- final reduce over 8 warps + tanh ----
        if (tid < 128) {
            int pq = tile*128 + tid;
            if (pq < TOTPAIRS) {
                float s = 0.f;
#pragma unroll
                for (int w = 0; w < 8; w++) s += red[w*128 + tid];
                g_sim[pq] = tanhf(s + b3s_sh);
            }
        }
        __syncthreads();
    }
}

// ---------------------------------------------------------------------------
// Kernel C: segment sums over pairs grouped by i  (warp per (n,i))
// ---------------------------------------------------------------------------
__global__ void seg_kernel(const int* __restrict__ skills,
                           const float* __restrict__ targets) {
    int r    = (blockIdx.x*blockDim.x + threadIdx.x) >> 5;
    int lane = threadIdx.x & 31;
    if (r >= ROWS) return;
    int n = r / HB, i = r % HB;
    const float* sp = g_sim + n*PP + i*(i-1)/2;
    float s = 0.f;
    for (int k = lane; k < i; k += 32) s += sp[k];
#pragma unroll
    for (int sh = 16; sh > 0; sh >>= 1) s += __shfl_xor_sync(0xffffffffu, s, sh);
    if (lane == 0) {
        float vt = (skills[r] != 0) ? s : 0.f;
        g_vt[r] = vt;
        g_vc[r] = vt * targets[r];
    }
}

// ---------------------------------------------------------------------------
// Kernel D: sparse final linear + BCE + sigmoid   (warp per row)
// ---------------------------------------------------------------------------
__global__ void final_kernel(const float* __restrict__ users,
                             const float* __restrict__ items,
                             const float* __restrict__ langs,
                             const int* __restrict__ skills,
                             const float* __restrict__ targets,
                             const int* __restrict__ mask,
                             const float* __restrict__ linW,
                             const float* __restrict__ linb,
                             float* __restrict__ out) {
    int r    = (blockIdx.x*blockDim.x + threadIdx.x) >> 5;
    int lane = threadIdx.x & 31;
    if (r >= ROWS) return;
    int n = r / HB;
    float acc = 0.f;
    const float* u = users + n*100;
    for (int k = lane; k < 100; k += 32) acc = fmaf(u[k], linW[k], acc);
    const float* it = items + r*100;
    for (int k = lane; k < 100; k += 32) acc = fmaf(it[k], linW[100+k], acc);
    if (lane < 10) acc = fmaf(langs[r*10 + lane], linW[200 + lane], acc);
#pragma unroll
    for (int sh = 16; sh > 0; sh >>= 1) acc += __shfl_xor_sync(0xffffffffu, acc, sh);
    if (lane == 0) {
        int s = skills[r];
        float logit = acc + linW[210 + s]
                    + g_vt[r]*linW[2210 + s]
                    + g_vc[r]*linW[4210 + s]
                    + linb[0];
        float label = targets[r];
        float maskf = (mask[r] != 0) ? 1.f : 0.f;
        float bce   = fmaxf(logit, 0.f) - logit*label + log1pf(expf(-fabsf(logit)));
        out[r]          = bce * maskf;
        out[ROWS + r]   = 1.f / (1.f + expf(-logit));
        out[2*ROWS + r] = label;
    }
}

// ---------------------------------------------------------------------------
extern "C" void kernel_launch(void* const* d_in, const int* in_sizes, int n_in,
                              void* d_out, int out_size) {
    const float* users    = (const float*)d_in[0];
    const float* items    = (const float*)d_in[1];
    const float* langs    = (const float*)d_in[2];
    const int*   skills   = (const int*)  d_in[3];
    const float* ts       = (const float*)d_in[4];
    const float* targets  = (const float*)d_in[5];
    const int*   mask     = (const int*)  d_in[6];
    const float* emb      = (const float*)d_in[7];
    const float* W1       = (const float*)d_in[8];
    const float* b1       = (const float*)d_in[9];
    const float* W2       = (const float*)d_in[10];
    const float* b2       = (const float*)d_in[11];
    const float* W3       = (const float*)d_in[12];
    const float* b3       = (const float*)d_in[13];
    const float* linW     = (const float*)d_in[14];
    const float* linb     = (const float*)d_in[15];
    float* out = (float*)d_out;

    size_t prepBytes = (size_t)(2*EMBD*H1D + RPB*EMBD) * sizeof(float);
    static int configured = -1;
    if (configured < 0) {
        cudaFuncSetAttribute(prep_kernel,
                             cudaFuncAttributeMaxDynamicSharedMemorySize,
                             (int)prepBytes);
        cudaFuncSetAttribute(pair_tc_kernel,
                             cudaFuncAttributeMaxDynamicSharedMemorySize,
                             SMEM_DYN);
        configured = 1;
    }

    prep_kernel<<<PREPBLK, 256, prepBytes>>>(skills, emb, W1, b1);
    pair_tc_kernel<<<TCGRID, 256, SMEM_DYN>>>(skills, ts, W2, b2, W3, b3);
    seg_kernel<<<(ROWS*32 + 255)/256, 256>>>(skills, targets);
    final_kernel<<<(ROWS*32 + 255)/256, 256>>>(users, items, langs, skills,
                                               targets, mask, linW, linb, out);
}

// round 11
// speedup vs baseline: 4.1603x; 1.2498x over previous
#include <cuda_runtime.h>
#include <cuda_bf16.h>
#include <math.h>
#include <stdint.h>

#define NB 16
#define HB 200
#define EMBD 64
#define H1D 128
#define H2D 64
#define PP 19900                 // H*(H-1)/2
#define ROWS (NB*HB)             // 3200
#define TOTPAIRS (NB*PP)         // 318400
#define W1COLS 134               // 2*EMB + 6

#define RPB 20                   // rows per prep block
#define PREPBLK 160

#define NTILES ((TOTPAIRS + 127) / 128)   // 2488
#define TCGRID 304

#define HSTRIDE_B 272            // h row stride in bytes (128 bf16 + 8 pad)
#define A_HI_OFF 0
#define A_LO_OFF 34816           // 128*272
#define RED_OFF  69632           // + 128*272
#define SMEM_DYN (RED_OFF + 8*128*4)   // 73728

// scratch (device globals; no allocation allowed)
__device__ float g_A[ROWS*H1D];      // e_i @ W1a^T
__device__ float g_B[ROWS*H1D];      // e_j @ W1b^T
__device__ float g_catb[6*H1D];      // W1c[:,cat] + b1
__device__ float g_sim[TOTPAIRS];

__device__ __forceinline__ uint32_t smem_to_u32(const void* p) {
    uint32_t a;
    asm("{ .reg .u64 t; cvta.to.shared.u64 t, %1; cvt.u32.u64 %0, t; }"
        : "=r"(a) : "l"(p));
    return a;
}

__device__ __forceinline__ void ldmatrix_x4(uint32_t& r0, uint32_t& r1,
                                            uint32_t& r2, uint32_t& r3,
                                            uint32_t addr) {
    asm volatile("ldmatrix.sync.aligned.m8n8.x4.shared.b16 {%0,%1,%2,%3}, [%4];"
                 : "=r"(r0), "=r"(r1), "=r"(r2), "=r"(r3) : "r"(addr));
}

__device__ __forceinline__ void mma_bf16(float& d0, float& d1, float& d2, float& d3,
                                         uint32_t a0, uint32_t a1, uint32_t a2, uint32_t a3,
                                         uint32_t b0, uint32_t b1) {
    asm volatile("mma.sync.aligned.m16n8k16.row.col.f32.bf16.bf16.f32 "
                 "{%0,%1,%2,%3}, {%4,%5,%6,%7}, {%8,%9}, {%0,%1,%2,%3};"
                 : "+f"(d0), "+f"(d1), "+f"(d2), "+f"(d3)
                 : "r"(a0), "r"(a1), "r"(a2), "r"(a3), "r"(b0), "r"(b1));
}

// ---------------------------------------------------------------------------
// Kernel A: coalesced, smem-tiled per-position projections (unchanged)
// ---------------------------------------------------------------------------
__global__ void __launch_bounds__(256, 1)
prep_kernel(const int* __restrict__ skills,
            const float* __restrict__ emb,
            const float* __restrict__ W1,
            const float* __restrict__ b1) {
    extern __shared__ float psm[];
    float* W1aT = psm;
    float* W1bT = W1aT + EMBD*H1D;
    float* es   = W1bT + EMBD*H1D;
    __shared__ int sk[RPB];

    int tid = threadIdx.x;
    int r0  = blockIdx.x * RPB;

    for (int idx = tid; idx < H1D*W1COLS; idx += 256) {
        int c = idx / W1COLS, j = idx - c*W1COLS;
        float v = W1[idx];
        if (j < EMBD)            W1aT[j*H1D + c] = v;
        else if (j < 2*EMBD)     W1bT[(j-EMBD)*H1D + c] = v;
        else if (blockIdx.x == 0) g_catb[(j-2*EMBD)*H1D + c] = v + b1[c];
    }
    if (tid < RPB) sk[tid] = skills[r0 + tid];
    __syncthreads();
    for (int idx = tid; idx < RPB*EMBD; idx += 256) {
        int row = idx >> 6, k = idx & 63;
        es[row*EMBD + k] = emb[sk[row]*EMBD + k];
    }
    __syncthreads();

    int rowh = tid >> 7;
    int c    = tid & 127;
    for (int rp = 0; rp < RPB; rp += 2) {
        int row = rp + rowh;
        const float* e = es + row*EMBD;
        float a = 0.f, b = 0.f;
#pragma unroll
        for (int k = 0; k < EMBD; k++) {
            float ev = e[k];
            a = fmaf(ev, W1aT[k*H1D + c], a);
            b = fmaf(ev, W1bT[k*H1D + c], b);
        }
        g_A[(r0+row)*H1D + c] = a;
        g_B[(r0+row)*H1D + c] = b;
    }
}

// ---------------------------------------------------------------------------
// Kernel B: tile = 128 pairs x 64 outputs. 8 warps; warp w owns cols [8w,8w+8).
// Phase 1 (FIXED): warp handles 16 pairs; LANES SPAN COLUMNS -> coalesced
// float4 loads of g_A/g_B and conflict-free STS. Pair indices broadcast by shfl.
// MMA phase identical to R9 (verified correct).
// ---------------------------------------------------------------------------
__global__ void __launch_bounds__(256, 2)
pair_tc_kernel(const int* __restrict__ skills,
               const float* __restrict__ ts,
               const float* __restrict__ W2,
               const float* __restrict__ b2,
               const float* __restrict__ W3,
               const float* __restrict__ b3) {
    extern __shared__ __align__(16) char smem[];
    float* red = (float*)(smem + RED_OFF);     // [8][128]

    __shared__ float catbs[6*H1D];
    __shared__ float b2s[H2D], W3s[H2D];
    __shared__ float b3s_sh;

    int tid = threadIdx.x, wid = tid >> 5, lane = tid & 31;
    int g = lane >> 2, t = lane & 3;
    int n0 = wid * 8;

    for (int idx = tid; idx < 6*H1D; idx += 256) catbs[idx] = g_catb[idx];
    if (tid < H2D) { b2s[tid] = b2[tid]; W3s[tid] = W3[tid]; }
    if (tid == 0) b3s_sh = b3[0];

    // ---- build W2 hi/lo B-fragments in registers (col = n0+g, rows = k) ----
    uint32_t bH[8][2], bL[8][2];
    {
        const float* wrow = W2 + (n0 + g) * H1D;
#pragma unroll
        for (int kt = 0; kt < 8; kt++) {
#pragma unroll
            for (int hb = 0; hb < 2; hb++) {
                int k0 = kt*16 + t*2 + hb*8;
                float w0 = wrow[k0], w1 = wrow[k0+1];
                __nv_bfloat16 h0 = __float2bfloat16(w0);
                __nv_bfloat16 h1 = __float2bfloat16(w1);
                __nv_bfloat162 hp; hp.x = h0; hp.y = h1;
                __nv_bfloat162 lp = __floats2bfloat162_rn(w0 - __bfloat162float(h0),
                                                          w1 - __bfloat162float(h1));
                bH[kt][hb] = *reinterpret_cast<uint32_t*>(&hp);
                bL[kt][hb] = *reinterpret_cast<uint32_t*>(&lp);
            }
        }
    }
    __syncthreads();

    uint32_t smem_base = smem_to_u32(smem);
    float b2a = b2s[n0 + t*2], b2b = b2s[n0 + t*2 + 1];
    float w3a = W3s[n0 + t*2], w3b = W3s[n0 + t*2 + 1];

    for (int tile = blockIdx.x; tile < NTILES; tile += TCGRID) {
        // ---- phase 1: per-lane pair indices for u = lane&15, then broadcast ----
        int ri_l, rj_l, cat_l;
        {
            int u_l = lane & 15;
            int pq = tile*128 + wid*16 + u_l;
            int q  = (pq < TOTPAIRS) ? pq : (TOTPAIRS - 1);
            int n  = q / PP, p = q - n*PP;
            int i = (int)((1.0f + sqrtf(1.0f + 8.0f*(float)p)) * 0.5f);
            while (i*(i-1)/2 > p)  --i;
            while ((i+1)*i/2 <= p) ++i;
            int j = p - i*(i-1)/2;
            ri_l = n*HB + i;
            rj_l = n*HB + j;
            float dt = ts[ri_l] - ts[rj_l];
            cat_l = 1 + (dt > 1.f) + (dt > 3600.f) + (dt > 86400.f) + (dt > 604800.f);
            if (skills[ri_l] == 0 || skills[rj_l] == 0) cat_l = 0;
        }
        {
            int c0 = lane * 4;
            char* baseHi = smem + A_HI_OFF + (wid*16)*HSTRIDE_B + c0*2;
            char* baseLo = smem + A_LO_OFF + (wid*16)*HSTRIDE_B + c0*2;
#pragma unroll 4
            for (int u = 0; u < 16; u++) {
                int ri  = __shfl_sync(0xffffffffu, ri_l, u);
                int rj  = __shfl_sync(0xffffffffu, rj_l, u);
                int cat = __shfl_sync(0xffffffffu, cat_l, u);
                float4 av = *(const float4*)(g_A + ri*H1D + c0);
                float4 bv = *(const float4*)(g_B + rj*H1D + c0);
                float4 cv = *(const float4*)(catbs + cat*H1D + c0);
                float h0 = fmaxf(av.x + bv.x + cv.x, 0.f);
                float h1 = fmaxf(av.y + bv.y + cv.y, 0.f);
                float h2 = fmaxf(av.z + bv.z + cv.z, 0.f);
                float h3 = fmaxf(av.w + bv.w + cv.w, 0.f);
                __nv_bfloat162 hp0; hp0.x = __float2bfloat16(h0); hp0.y = __float2bfloat16(h1);
                __nv_bfloat162 hp1; hp1.x = __float2bfloat16(h2); hp1.y = __float2bfloat16(h3);
                float2 f0 = __bfloat1622float2(hp0);
                float2 f1 = __bfloat1622float2(hp1);
                __nv_bfloat162 lp0 = __floats2bfloat162_rn(h0 - f0.x, h1 - f0.y);
                __nv_bfloat162 lp1 = __floats2bfloat162_rn(h2 - f1.x, h3 - f1.y);
                uint2 hv, lv;
                hv.x = *reinterpret_cast<uint32_t*>(&hp0);
                hv.y = *reinterpret_cast<uint32_t*>(&hp1);
                lv.x = *reinterpret_cast<uint32_t*>(&lp0);
                lv.y = *reinterpret_cast<uint32_t*>(&lp1);
                *(uint2*)(baseHi + u*HSTRIDE_B) = hv;
                *(uint2*)(baseLo + u*HSTRIDE_B) = lv;
            }
        }
        __syncthreads();

        // ---- MMA + per-mt epilogue (unchanged from R9) ----
        {
            uint32_t laddrHi = smem_base + A_HI_OFF
                             + (uint32_t)(lane & 15) * HSTRIDE_B
                             + (uint32_t)(lane >> 4) * 16;
            uint32_t laddrLo = laddrHi + (A_LO_OFF - A_HI_OFF);
#pragma unroll
            for (int mt = 0; mt < 8; mt++) {
                float d0 = 0.f, d1 = 0.f, d2 = 0.f, d3 = 0.f;
                uint32_t mOff = (uint32_t)(mt*16) * HSTRIDE_B;
#pragma unroll
                for (int kt = 0; kt < 8; kt++) {
                    uint32_t aH0,aH1,aH2,aH3, aL0,aL1,aL2,aL3;
                    ldmatrix_x4(aH0,aH1,aH2,aH3, laddrHi + mOff + kt*32);
                    ldmatrix_x4(aL0,aL1,aL2,aL3, laddrLo + mOff + kt*32);
                    mma_bf16(d0,d1,d2,d3, aH0,aH1,aH2,aH3, bH[kt][0], bH[kt][1]);
                    mma_bf16(d0,d1,d2,d3, aL0,aL1,aL2,aL3, bH[kt][0], bH[kt][1]);
                    mma_bf16(d0,d1,d2,d3, aH0,aH1,aH2,aH3, bL[kt][0], bL[kt][1]);
                }
                float p0 = fmaf(fmaxf(d0 + b2a, 0.f), w3a, fmaxf(d1 + b2b, 0.f) * w3b);
                float p1 = fmaf(fmaxf(d2 + b2a, 0.f), w3a, fmaxf(d3 + b2b, 0.f) * w3b);
                p0 += __shfl_xor_sync(0xffffffffu, p0, 1);
                p0 += __shfl_xor_sync(0xffffffffu, p0, 2);
                p1 += __shfl_xor_sync(0xffffffffu, p1, 1);
                p1 += __shfl_xor_sync(0xffffffffu, p1, 2);
                if (t == 0) {
                    red[wid*128 + mt*16 + g]     = p0;
                    red[wid*128 + mt*16 + 8 + g] = p1;
                }
            }
        }
        __syncthreads();

        if (tid < 128) {
            int pq = tile*128 + tid;
            if (pq < TOTPAIRS) {
                float s = 0.f;
#pragma unroll
                for (int w = 0; w < 8; w++) s += red[w*128 + tid];
                g_sim[pq] = tanhf(s + b3s_sh);
            }
        }
        __syncthreads();
    }
}

// ---------------------------------------------------------------------------
// Kernel C (fused seg+final): warp per row r.
//   1) segment-sum g_sim over pairs with i == r%HB  -> vt, vc
//   2) sparse final linear + BCE + sigmoid
// out layout: [0:3200) loss, [3200:6400) sigmoid(pred), [6400:9600) labels
// ---------------------------------------------------------------------------
__global__ void final_kernel(const float* __restrict__ users,
                             const float* __restrict__ items,
                             const float* __restrict__ langs,
                             const int* __restrict__ skills,
                             const float* __restrict__ targets,
                             const int* __restrict__ mask,
                             const float* __restrict__ linW,
                             const float* __restrict__ linb,
                             float* __restrict__ out) {
    int r    = (blockIdx.x*blockDim.x + threadIdx.x) >> 5;
    int lane = threadIdx.x & 31;
    if (r >= ROWS) return;
    int n = r / HB, i = r % HB;

    // segment sum over pairs grouped by i
    const float* sp = g_sim + n*PP + i*(i-1)/2;
    float s = 0.f;
    for (int k = lane; k < i; k += 32) s += sp[k];

    // final linear dot
    float acc = 0.f;
    const float* u = users + n*100;
    for (int k = lane; k < 100; k += 32) acc = fmaf(u[k], linW[k], acc);
    const float* it = items + r*100;
    for (int k = lane; k < 100; k += 32) acc = fmaf(it[k], linW[100+k], acc);
    if (lane < 10) acc = fmaf(langs[r*10 + lane], linW[200 + lane], acc);

#pragma unroll
    for (int sh = 16; sh > 0; sh >>= 1) {
        s   += __shfl_xor_sync(0xffffffffu, s,   sh);
        acc += __shfl_xor_sync(0xffffffffu, acc, sh);
    }
    if (lane == 0) {
        int sidx = skills[r];
        float label = targets[r];
        float vt = (sidx != 0) ? s : 0.f;
        float vc = vt * label;
        float logit = acc + linW[210 + sidx]
                    + vt*linW[2210 + sidx]
                    + vc*linW[4210 + sidx]
                    + linb[0];
        float maskf = (mask[r] != 0) ? 1.f : 0.f;
        float bce   = fmaxf(logit, 0.f) - logit*label + log1pf(expf(-fabsf(logit)));
        out[r]          = bce * maskf;
        out[ROWS + r]   = 1.f / (1.f + expf(-logit));
        out[2*ROWS + r] = label;
    }
}

// ---------------------------------------------------------------------------
extern "C" void kernel_launch(void* const* d_in, const int* in_sizes, int n_in,
                              void* d_out, int out_size) {
    const float* users    = (const float*)d_in[0];
    const float* items    = (const float*)d_in[1];
    const float* langs    = (const float*)d_in[2];
    const int*   skills   = (const int*)  d_in[3];
    const float* ts       = (const float*)d_in[4];
    const float* targets  = (const float*)d_in[5];
    const int*   mask     = (const int*)  d_in[6];
    const float* emb      = (const float*)d_in[7];
    const float* W1       = (const float*)d_in[8];
    const float* b1       = (const float*)d_in[9];
    const float* W2       = (const float*)d_in[10];
    const float* b2       = (const float*)d_in[11];
    const float* W3       = (const float*)d_in[12];
    const float* b3       = (const float*)d_in[13];
    const float* linW     = (const float*)d_in[14];
    const float* linb     = (const float*)d_in[15];
    float* out = (float*)d_out;

    size_t prepBytes = (size_t)(2*EMBD*H1D + RPB*EMBD) * sizeof(float);
    static int configured = -1;
    if (configured < 0) {
        cudaFuncSetAttribute(prep_kernel,
                             cudaFuncAttributeMaxDynamicSharedMemorySize,
                             (int)prepBytes);
        cudaFuncSetAttribute(pair_tc_kernel,
                             cudaFuncAttributeMaxDynamicSharedMemorySize,
                             SMEM_DYN);
        configured = 1;
    }

    prep_kernel<<<PREPBLK, 256, prepBytes>>>(skills, emb, W1, b1);
    pair_tc_kernel<<<TCGRID, 256, SMEM_DYN>>>(skills, ts, W2, b2, W3, b3);
    final_kernel<<<(ROWS*32 + 255)/256, 256>>>(users, items, langs, skills,
                                               targets, mask, linW, linb, out);
}

// round 13
// speedup vs baseline: 4.2596x; 1.0239x over previous
#include <cuda_runtime.h>
#include <cuda_bf16.h>
#include <math.h>
#include <stdint.h>

#define NB 16
#define HB 200
#define EMBD 64
#define H1D 128
#define H2D 64
#define PP 19900                 // H*(H-1)/2
#define ROWS (NB*HB)             // 3200
#define TOTPAIRS (NB*PP)         // 318400
#define W1COLS 134               // 2*EMB + 6

#define RPB 20                   // rows per prep block
#define PREPBLK 160
#define PTHREADS 640             // 20 warps

#define NTILES ((TOTPAIRS + 127) / 128)   // 2488
#define TCGRID 304

#define HSTRIDE_B 272            // h row stride in bytes (128 bf16 + 8 pad)
#define A_HI_OFF 0
#define A_LO_OFF 34816           // 128*272
#define RED_OFF  69632           // + 128*272
#define SMEM_DYN (RED_OFF + 8*128*4)   // 73728

// scratch (device globals; no allocation allowed)
__device__ float g_A[ROWS*H1D];      // e_i @ W1a^T
__device__ float g_B[ROWS*H1D];      // e_j @ W1b^T
__device__ float g_catb[6*H1D];      // W1c[:,cat] + b1
__device__ float g_sim[TOTPAIRS];

__device__ __forceinline__ uint32_t smem_to_u32(const void* p) {
    uint32_t a;
    asm("{ .reg .u64 t; cvta.to.shared.u64 t, %1; cvt.u32.u64 %0, t; }"
        : "=r"(a) : "l"(p));
    return a;
}

__device__ __forceinline__ void ldmatrix_x4(uint32_t& r0, uint32_t& r1,
                                            uint32_t& r2, uint32_t& r3,
                                            uint32_t addr) {
    asm volatile("ldmatrix.sync.aligned.m8n8.x4.shared.b16 {%0,%1,%2,%3}, [%4];"
                 : "=r"(r0), "=r"(r1), "=r"(r2), "=r"(r3) : "r"(addr));
}

__device__ __forceinline__ void mma_bf16(float& d0, float& d1, float& d2, float& d3,
                                         uint32_t a0, uint32_t a1, uint32_t a2, uint32_t a3,
                                         uint32_t b0, uint32_t b1) {
    asm volatile("mma.sync.aligned.m16n8k16.row.col.f32.bf16.bf16.f32 "
                 "{%0,%1,%2,%3}, {%4,%5,%6,%7}, {%8,%9}, {%0,%1,%2,%3};"
                 : "+f"(d0), "+f"(d1), "+f"(d2), "+f"(d3)
                 : "r"(a0), "r"(a1), "r"(a2), "r"(a3), "r"(b0), "r"(b1));
}

// ---------------------------------------------------------------------------
// Kernel A (ILP rewrite): 160 blocks x 640 threads. Threads: c = tid&127,
// row-pair = tid>>7 (0..4). Each thread computes 2 rows at once (4 indep FMA
// chains, W-loads amortized over rows). 2 passes x 10 rows cover RPB=20.
// ---------------------------------------------------------------------------
__global__ void __launch_bounds__(PTHREADS, 1)
prep_kernel(const int* __restrict__ skills,
            const float* __restrict__ emb,
            const float* __restrict__ W1,
            const float* __restrict__ b1) {
    extern __shared__ float psm[];
    float* W1aT = psm;                 // [k][c] 64x128
    float* W1bT = W1aT + EMBD*H1D;     // [k][c] 64x128
    float* es   = W1bT + EMBD*H1D;     // [row][k] RPB x 64
    __shared__ int sk[RPB];

    int tid = threadIdx.x;
    int r0  = blockIdx.x * RPB;

    for (int idx = tid; idx < H1D*W1COLS; idx += PTHREADS) {
        int c = idx / W1COLS, j = idx - c*W1COLS;
        float v = W1[idx];
        if (j < EMBD)            W1aT[j*H1D + c] = v;
        else if (j < 2*EMBD)     W1bT[(j-EMBD)*H1D + c] = v;
        else if (blockIdx.x == 0) g_catb[(j-2*EMBD)*H1D + c] = v + b1[c];
    }
    if (tid < RPB) sk[tid] = skills[r0 + tid];
    __syncthreads();
    for (int idx = tid; idx < RPB*EMBD; idx += PTHREADS) {
        int row = idx >> 6, k = idx & 63;
        es[row*EMBD + k] = emb[sk[row]*EMBD + k];
    }
    __syncthreads();

    int c     = tid & 127;
    int rpair = tid >> 7;              // 0..4
#pragma unroll
    for (int pass = 0; pass < 2; pass++) {
        int row0 = pass*10 + rpair*2;
        const float* e0 = es + row0*EMBD;
        const float* e1 = e0 + EMBD;
        float a0 = 0.f, a1 = 0.f, bb0 = 0.f, bb1 = 0.f;
#pragma unroll
        for (int k = 0; k < EMBD; k++) {
            float wa  = W1aT[k*H1D + c];
            float wb  = W1bT[k*H1D + c];
            float ev0 = e0[k], ev1 = e1[k];
            a0  = fmaf(ev0, wa, a0);
            a1  = fmaf(ev1, wa, a1);
            bb0 = fmaf(ev0, wb, bb0);
            bb1 = fmaf(ev1, wb, bb1);
        }
        g_A[(r0+row0  )*H1D + c] = a0;
        g_A[(r0+row0+1)*H1D + c] = a1;
        g_B[(r0+row0  )*H1D + c] = bb0;
        g_B[(r0+row0+1)*H1D + c] = bb1;
    }
}

// ---------------------------------------------------------------------------
// Kernel B: tile = 128 pairs x 64 outputs. 8 warps; warp w owns cols [8w,8w+8).
// (unchanged from R11)
// ---------------------------------------------------------------------------
__global__ void __launch_bounds__(256, 2)
pair_tc_kernel(const int* __restrict__ skills,
               const float* __restrict__ ts,
               const float* __restrict__ W2,
               const float* __restrict__ b2,
               const float* __restrict__ W3,
               const float* __restrict__ b3) {
    extern __shared__ __align__(16) char smem[];
    float* red = (float*)(smem + RED_OFF);     // [8][128]

    __shared__ float catbs[6*H1D];
    __shared__ float b2s[H2D], W3s[H2D];
    __shared__ float b3s_sh;

    int tid = threadIdx.x, wid = tid >> 5, lane = tid & 31;
    int g = lane >> 2, t = lane & 3;
    int n0 = wid * 8;

    for (int idx = tid; idx < 6*H1D; idx += 256) catbs[idx] = g_catb[idx];
    if (tid < H2D) { b2s[tid] = b2[tid]; W3s[tid] = W3[tid]; }
    if (tid == 0) b3s_sh = b3[0];

    // ---- build W2 hi/lo B-fragments in registers (col = n0+g, rows = k) ----
    uint32_t bH[8][2], bL[8][2];
    {
        const float* wrow = W2 + (n0 + g) * H1D;
#pragma unroll
        for (int kt = 0; kt < 8; kt++) {
#pragma unroll
            for (int hb = 0; hb < 2; hb++) {
                int k0 = kt*16 + t*2 + hb*8;
                float w0 = wrow[k0], w1 = wrow[k0+1];
                __nv_bfloat16 h0 = __float2bfloat16(w0);
                __nv_bfloat16 h1 = __float2bfloat16(w1);
                __nv_bfloat162 hp; hp.x = h0; hp.y = h1;
                __nv_bfloat162 lp = __floats2bfloat162_rn(w0 - __bfloat162float(h0),
                                                          w1 - __bfloat162float(h1));
                bH[kt][hb] = *reinterpret_cast<uint32_t*>(&hp);
                bL[kt][hb] = *reinterpret_cast<uint32_t*>(&lp);
            }
        }
    }
    __syncthreads();

    uint32_t smem_base = smem_to_u32(smem);
    float b2a = b2s[n0 + t*2], b2b = b2s[n0 + t*2 + 1];
    float w3a = W3s[n0 + t*2], w3b = W3s[n0 + t*2 + 1];

    for (int tile = blockIdx.x; tile < NTILES; tile += TCGRID) {
        // ---- phase 1: per-lane pair indices for u = lane&15, then broadcast ----
        int ri_l, rj_l, cat_l;
        {
            int u_l = lane & 15;
            int pq = tile*128 + wid*16 + u_l;
            int q  = (pq < TOTPAIRS) ? pq : (TOTPAIRS - 1);
            int n  = q / PP, p = q - n*PP;
            int i = (int)((1.0f + sqrtf(1.0f + 8.0f*(float)p)) * 0.5f);
            while (i*(i-1)/2 > p)  --i;
            while ((i+1)*i/2 <= p) ++i;
            int j = p - i*(i-1)/2;
            ri_l = n*HB + i;
            rj_l = n*HB + j;
            float dt = ts[ri_l] - ts[rj_l];
            cat_l = 1 + (dt > 1.f) + (dt > 3600.f) + (dt > 86400.f) + (dt > 604800.f);
            if (skills[ri_l] == 0 || skills[rj_l] == 0) cat_l = 0;
        }
        {
            int c0 = lane * 4;
            char* baseHi = smem + A_HI_OFF + (wid*16)*HSTRIDE_B + c0*2;
            char* baseLo = smem + A_LO_OFF + (wid*16)*HSTRIDE_B + c0*2;
#pragma unroll 4
            for (int u = 0; u < 16; u++) {
                int ri  = __shfl_sync(0xffffffffu, ri_l, u);
                int rj  = __shfl_sync(0xffffffffu, rj_l, u);
                int cat = __shfl_sync(0xffffffffu, cat_l, u);
                float4 av = *(const float4*)(g_A + ri*H1D + c0);
                float4 bv = *(const float4*)(g_B + rj*H1D + c0);
                float4 cv = *(const float4*)(catbs + cat*H1D + c0);
                float h0 = fmaxf(av.x + bv.x + cv.x, 0.f);
                float h1 = fmaxf(av.y + bv.y + cv.y, 0.f);
                float h2 = fmaxf(av.z + bv.z + cv.z, 0.f);
                float h3 = fmaxf(av.w + bv.w + cv.w, 0.f);
                __nv_bfloat162 hp0; hp0.x = __float2bfloat16(h0); hp0.y = __float2bfloat16(h1);
                __nv_bfloat162 hp1; hp1.x = __float2bfloat16(h2); hp1.y = __float2bfloat16(h3);
                float2 f0 = __bfloat1622float2(hp0);
                float2 f1 = __bfloat1622float2(hp1);
                __nv_bfloat162 lp0 = __floats2bfloat162_rn(h0 - f0.x, h1 - f0.y);
                __nv_bfloat162 lp1 = __floats2bfloat162_rn(h2 - f1.x, h3 - f1.y);
                uint2 hv, lv;
                hv.x = *reinterpret_cast<uint32_t*>(&hp0);
                hv.y = *reinterpret_cast<uint32_t*>(&hp1);
                lv.x = *reinterpret_cast<uint32_t*>(&lp0);
                lv.y = *reinterpret_cast<uint32_t*>(&lp1);
                *(uint2*)(baseHi + u*HSTRIDE_B) = hv;
                *(uint2*)(baseLo + u*HSTRIDE_B) = lv;
            }
        }
        __syncthreads();

        // ---- MMA + per-mt epilogue ----
        {
            uint32_t laddrHi = smem_base + A_HI_OFF
                             + (uint32_t)(lane & 15) * HSTRIDE_B
                             + (uint32_t)(lane >> 4) * 16;
            uint32_t laddrLo = laddrHi + (A_LO_OFF - A_HI_OFF);
#pragma unroll
            for (int mt = 0; mt < 8; mt++) {
                float d0 = 0.f, d1 = 0.f, d2 = 0.f, d3 = 0.f;
                uint32_t mOff = (uint32_t)(mt*16) * HSTRIDE_B;
#pragma unroll
                for (int kt = 0; kt < 8; kt++) {
                    uint32_t aH0,aH1,aH2,aH3, aL0,aL1,aL2,aL3;
                    ldmatrix_x4(aH0,aH1,aH2,aH3, laddrHi + mOff + kt*32);
                    ldmatrix_x4(aL0,aL1,aL2,aL3, laddrLo + mOff + kt*32);
                    mma_bf16(d0,d1,d2,d3, aH0,aH1,aH2,aH3, bH[kt][0], bH[kt][1]);
                    mma_bf16(d0,d1,d2,d3, aL0,aL1,aL2,aL3, bH[kt][0], bH[kt][1]);
                    mma_bf16(d0,d1,d2,d3, aH0,aH1,aH2,aH3, bL[kt][0], bL[kt][1]);
                }
                float p0 = fmaf(fmaxf(d0 + b2a, 0.f), w3a, fmaxf(d1 + b2b, 0.f) * w3b);
                float p1 = fmaf(fmaxf(d2 + b2a, 0.f), w3a, fmaxf(d3 + b2b, 0.f) * w3b);
                p0 += __shfl_xor_sync(0xffffffffu, p0, 1);
                p0 += __shfl_xor_sync(0xffffffffu, p0, 2);
                p1 += __shfl_xor_sync(0xffffffffu, p1, 1);
                p1 += __shfl_xor_sync(0xffffffffu, p1, 2);
                if (t == 0) {
                    red[wid*128 + mt*16 + g]     = p0;
                    red[wid*128 + mt*16 + 8 + g] = p1;
                }
            }
        }
        __syncthreads();

        if (tid < 128) {
            int pq = tile*128 + tid;
            if (pq < TOTPAIRS) {
                float s = 0.f;
#pragma unroll
                for (int w = 0; w < 8; w++) s += red[w*128 + tid];
                g_sim[pq] = tanhf(s + b3s_sh);
            }
        }
        __syncthreads();
    }
}

// ---------------------------------------------------------------------------
// Kernel C (fused seg+final): warp per row r. (unchanged)
// ---------------------------------------------------------------------------
__global__ void final_kernel(const float* __restrict__ users,
                             const float* __restrict__ items,
                             const float* __restrict__ langs,
                             const int* __restrict__ skills,
                             const float* __restrict__ targets,
                             const int* __restrict__ mask,
                             const float* __restrict__ linW,
                             const float* __restrict__ linb,
                             float* __restrict__ out) {
    int r    = (blockIdx.x*blockDim.x + threadIdx.x) >> 5;
    int lane = threadIdx.x & 31;
    if (r >= ROWS) return;
    int n = r / HB, i = r % HB;

    const float* sp = g_sim + n*PP + i*(i-1)/2;
    float s = 0.f;
    for (int k = lane; k < i; k += 32) s += sp[k];

    float acc = 0.f;
    const float* u = users + n*100;
    for (int k = lane; k < 100; k += 32) acc = fmaf(u[k], linW[k], acc);
    const float* it = items + r*100;
    for (int k = lane; k < 100; k += 32) acc = fmaf(it[k], linW[100+k], acc);
    if (lane < 10) acc = fmaf(langs[r*10 + lane], linW[200 + lane], acc);

#pragma unroll
    for (int sh = 16; sh > 0; sh >>= 1) {
        s   += __shfl_xor_sync(0xffffffffu, s,   sh);
        acc += __shfl_xor_sync(0xffffffffu, acc, sh);
    }
    if (lane == 0) {
        int sidx = skills[r];
        float label = targets[r];
        float vt = (sidx != 0) ? s : 0.f;
        float vc = vt * label;
        float logit = acc + linW[210 + sidx]
                    + vt*linW[2210 + sidx]
                    + vc*linW[4210 + sidx]
                    + linb[0];
        float maskf = (mask[r] != 0) ? 1.f : 0.f;
        float bce   = fmaxf(logit, 0.f) - logit*label + log1pf(expf(-fabsf(logit)));
        out[r]          = bce * maskf;
        out[ROWS + r]   = 1.f / (1.f + expf(-logit));
        out[2*ROWS + r] = label;
    }
}

// ---------------------------------------------------------------------------
extern "C" void kernel_launch(void* const* d_in, const int* in_sizes, int n_in,
                              void* d_out, int out_size) {
    const float* users    = (const float*)d_in[0];
    const float* items    = (const float*)d_in[1];
    const float* langs    = (const float*)d_in[2];
    const int*   skills   = (const int*)  d_in[3];
    const float* ts       = (const float*)d_in[4];
    const float* targets  = (const float*)d_in[5];
    const int*   mask     = (const int*)  d_in[6];
    const float* emb      = (const float*)d_in[7];
    const float* W1       = (const float*)d_in[8];
    const float* b1       = (const float*)d_in[9];
    const float* W2       = (const float*)d_in[10];
    const float* b2       = (const float*)d_in[11];
    const float* W3       = (const float*)d_in[12];
    const float* b3       = (const float*)d_in[13];
    const float* linW     = (const float*)d_in[14];
    const float* linb     = (const float*)d_in[15];
    float* out = (float*)d_out;

    size_t prepBytes = (size_t)(2*EMBD*H1D + RPB*EMBD) * sizeof(float);
    static int configured = -1;
    if (configured < 0) {
        cudaFuncSetAttribute(prep_kernel,
                             cudaFuncAttributeMaxDynamicSharedMemorySize,
                             (int)prepBytes);
        cudaFuncSetAttribute(pair_tc_kernel,
                             cudaFuncAttributeMaxDynamicSharedMemorySize,
                             SMEM_DYN);
        configured = 1;
    }

    prep_kernel<<<PREPBLK, PTHREADS, prepBytes>>>(skills, emb, W1, b1);
    pair_tc_kernel<<<TCGRID, 256, SMEM_DYN>>>(skills, ts, W2, b2, W3, b3);
    final_kernel<<<(ROWS*32 + 255)/256, 256>>>(users, items, langs, skills,
                                               targets, mask, linW, linb, out);
}

// round 14
// speedup vs baseline: 4.5415x; 1.0662x over previous
#include <cuda_runtime.h>
#include <cuda_bf16.h>
#include <math.h>
#include <stdint.h>

#define NB 16
#define HB 200
#define EMBD 64
#define H1D 128
#define H2D 64
#define PP 19900                 // H*(H-1)/2
#define ROWS (NB*HB)             // 3200
#define TOTPAIRS (NB*PP)         // 318400
#define W1COLS 134               // 2*EMB + 6

#define RPB 10                   // rows per prep block
#define PREPBLK 320
#define PTHREADS 640             // 20 warps

#define NTILES ((TOTPAIRS + 127) / 128)   // 2488
#define TCGRID 304

#define HSTRIDE_B 272            // h row stride in bytes (128 bf16 + 8 pad)
#define A_HI_OFF 0
#define A_LO_OFF 34816           // 128*272
#define RED_OFF  69632           // + 128*272
#define SMEM_DYN (RED_OFF + 4*128*4)   // 71680

// scratch (device globals; no allocation allowed)
__device__ float g_A[ROWS*H1D];      // e_i @ W1a^T
__device__ float g_B[ROWS*H1D];      // e_j @ W1b^T
__device__ float g_catb[6*H1D];      // W1c[:,cat] + b1
__device__ float g_sim[TOTPAIRS];

__device__ __forceinline__ uint32_t smem_to_u32(const void* p) {
    uint32_t a;
    asm("{ .reg .u64 t; cvta.to.shared.u64 t, %1; cvt.u32.u64 %0, t; }"
        : "=r"(a) : "l"(p));
    return a;
}

__device__ __forceinline__ void ldmatrix_x4(uint32_t& r0, uint32_t& r1,
                                            uint32_t& r2, uint32_t& r3,
                                            uint32_t addr) {
    asm volatile("ldmatrix.sync.aligned.m8n8.x4.shared.b16 {%0,%1,%2,%3}, [%4];"
                 : "=r"(r0), "=r"(r1), "=r"(r2), "=r"(r3) : "r"(addr));
}

__device__ __forceinline__ void mma_bf16(float& d0, float& d1, float& d2, float& d3,
                                         uint32_t a0, uint32_t a1, uint32_t a2, uint32_t a3,
                                         uint32_t b0, uint32_t b1) {
    asm volatile("mma.sync.aligned.m16n8k16.row.col.f32.bf16.bf16.f32 "
                 "{%0,%1,%2,%3}, {%4,%5,%6,%7}, {%8,%9}, {%0,%1,%2,%3};"
                 : "+f"(d0), "+f"(d1), "+f"(d2), "+f"(d3)
                 : "r"(a0), "r"(a1), "r"(a2), "r"(a3), "r"(b0), "r"(b1));
}

// ---------------------------------------------------------------------------
// Kernel A: 320 blocks x 640 threads, 2 blocks/SM. RPB=10 rows per block,
// one pass (rpair = tid>>7 covers 0..4, 2 rows each, 4 indep FMA chains).
// ---------------------------------------------------------------------------
__global__ void __launch_bounds__(PTHREADS, 2)
prep_kernel(const int* __restrict__ skills,
            const float* __restrict__ emb,
            const float* __restrict__ W1,
            const float* __restrict__ b1) {
    extern __shared__ float psm[];
    float* W1aT = psm;                 // [k][c] 64x128
    float* W1bT = W1aT + EMBD*H1D;     // [k][c] 64x128
    float* es   = W1bT + EMBD*H1D;     // [row][k] RPB x 64
    __shared__ int sk[RPB];

    int tid = threadIdx.x;
    int r0  = blockIdx.x * RPB;

    for (int idx = tid; idx < H1D*W1COLS; idx += PTHREADS) {
        int c = idx / W1COLS, j = idx - c*W1COLS;
        float v = W1[idx];
        if (j < EMBD)            W1aT[j*H1D + c] = v;
        else if (j < 2*EMBD)     W1bT[(j-EMBD)*H1D + c] = v;
        else if (blockIdx.x == 0) g_catb[(j-2*EMBD)*H1D + c] = v + b1[c];
    }
    if (tid < RPB) sk[tid] = skills[r0 + tid];
    __syncthreads();
    for (int idx = tid; idx < RPB*EMBD; idx += PTHREADS) {
        int row = idx >> 6, k = idx & 63;
        es[row*EMBD + k] = emb[sk[row]*EMBD + k];
    }
    __syncthreads();

    int c     = tid & 127;
    int rpair = tid >> 7;              // 0..4
    int row0  = rpair*2;
    const float* e0 = es + row0*EMBD;
    const float* e1 = e0 + EMBD;
    float a0 = 0.f, a1 = 0.f, bb0 = 0.f, bb1 = 0.f;
#pragma unroll
    for (int k = 0; k < EMBD; k++) {
        float wa  = W1aT[k*H1D + c];
        float wb  = W1bT[k*H1D + c];
        float ev0 = e0[k], ev1 = e1[k];
        a0  = fmaf(ev0, wa, a0);
        a1  = fmaf(ev1, wa, a1);
        bb0 = fmaf(ev0, wb, bb0);
        bb1 = fmaf(ev1, wb, bb1);
    }
    g_A[(r0+row0  )*H1D + c] = a0;
    g_A[(r0+row0+1)*H1D + c] = a1;
    g_B[(r0+row0  )*H1D + c] = bb0;
    g_B[(r0+row0+1)*H1D + c] = bb1;
}

// ---------------------------------------------------------------------------
// Kernel B: tile = 128 pairs x 64 outputs.
// Warp split: mhalf = wid>>2 (rows 64*mhalf..+63), nq = wid&3 (cols 16*nq..+15).
// Each warp: 4 mt x 8 kt x (2 LDSM + 6 mma)  -> LDSM halved vs n-only split.
// ---------------------------------------------------------------------------
__global__ void __launch_bounds__(256, 2)
pair_tc_kernel(const int* __restrict__ skills,
               const float* __restrict__ ts,
               const float* __restrict__ W2,
               const float* __restrict__ b2,
               const float* __restrict__ W3,
               const float* __restrict__ b3) {
    extern __shared__ __align__(16) char smem[];
    float* red = (float*)(smem + RED_OFF);     // [4][128]

    __shared__ float catbs[6*H1D];
    __shared__ float b2s[H2D], W3s[H2D];
    __shared__ float b3s_sh;

    int tid = threadIdx.x, wid = tid >> 5, lane = tid & 31;
    int g = lane >> 2, t = lane & 3;
    int mhalf = wid >> 2;          // 0,1 : rows [64*mhalf, 64*mhalf+64)
    int nq    = wid & 3;           // 0..3: cols [16*nq, 16*nq+16)
    int n0    = nq * 16;

    for (int idx = tid; idx < 6*H1D; idx += 256) catbs[idx] = g_catb[idx];
    if (tid < H2D) { b2s[tid] = b2[tid]; W3s[tid] = W3[tid]; }
    if (tid == 0) b3s_sh = b3[0];

    // ---- W2 hi/lo B-fragments: ng=0 -> col n0+g, ng=1 -> col n0+8+g ----
    uint32_t bH[8][4], bL[8][4];
#pragma unroll
    for (int ng = 0; ng < 2; ng++) {
        const float* wrow = W2 + (n0 + ng*8 + g) * H1D;
#pragma unroll
        for (int kt = 0; kt < 8; kt++) {
#pragma unroll
            for (int hb = 0; hb < 2; hb++) {
                int k0 = kt*16 + t*2 + hb*8;
                float w0 = wrow[k0], w1 = wrow[k0+1];
                __nv_bfloat16 h0 = __float2bfloat16(w0);
                __nv_bfloat16 h1 = __float2bfloat16(w1);
                __nv_bfloat162 hp; hp.x = h0; hp.y = h1;
                __nv_bfloat162 lp = __floats2bfloat162_rn(w0 - __bfloat162float(h0),
                                                          w1 - __bfloat162float(h1));
                bH[kt][ng*2+hb] = *reinterpret_cast<uint32_t*>(&hp);
                bL[kt][ng*2+hb] = *reinterpret_cast<uint32_t*>(&lp);
            }
        }
    }
    __syncthreads();

    uint32_t smem_base = smem_to_u32(smem);
    // epilogue constants: ngroup 0 cols n0+t*2,+1 ; ngroup 1 cols n0+8+t*2,+1
    float b2c[2][2], w3c[2][2];
#pragma unroll
    for (int ng = 0; ng < 2; ng++) {
        b2c[ng][0] = b2s[n0 + ng*8 + t*2];
        b2c[ng][1] = b2s[n0 + ng*8 + t*2 + 1];
        w3c[ng][0] = W3s[n0 + ng*8 + t*2];
        w3c[ng][1] = W3s[n0 + ng*8 + t*2 + 1];
    }

    for (int tile = blockIdx.x; tile < NTILES; tile += TCGRID) {
        // ---- phase 1: per-lane pair indices for u = lane&15, then broadcast ----
        int ri_l, rj_l, cat_l;
        {
            int u_l = lane & 15;
            int pq = tile*128 + wid*16 + u_l;
            int q  = (pq < TOTPAIRS) ? pq : (TOTPAIRS - 1);
            int n  = q / PP, p = q - n*PP;
            int i = (int)((1.0f + sqrtf(1.0f + 8.0f*(float)p)) * 0.5f);
            while (i*(i-1)/2 > p)  --i;
            while ((i+1)*i/2 <= p) ++i;
            int j = p - i*(i-1)/2;
            ri_l = n*HB + i;
            rj_l = n*HB + j;
            float dt = ts[ri_l] - ts[rj_l];
            cat_l = 1 + (dt > 1.f) + (dt > 3600.f) + (dt > 86400.f) + (dt > 604800.f);
            if (skills[ri_l] == 0 || skills[rj_l] == 0) cat_l = 0;
        }
        {
            int c0 = lane * 4;
            char* baseHi = smem + A_HI_OFF + (wid*16)*HSTRIDE_B + c0*2;
            char* baseLo = smem + A_LO_OFF + (wid*16)*HSTRIDE_B + c0*2;
#pragma unroll 4
            for (int u = 0; u < 16; u++) {
                int ri  = __shfl_sync(0xffffffffu, ri_l, u);
                int rj  = __shfl_sync(0xffffffffu, rj_l, u);
                int cat = __shfl_sync(0xffffffffu, cat_l, u);
                float4 av = *(const float4*)(g_A + ri*H1D + c0);
                float4 bv = *(const float4*)(g_B + rj*H1D + c0);
                float4 cv = *(const float4*)(catbs + cat*H1D + c0);
                float h0 = fmaxf(av.x + bv.x + cv.x, 0.f);
                float h1 = fmaxf(av.y + bv.y + cv.y, 0.f);
                float h2 = fmaxf(av.z + bv.z + cv.z, 0.f);
                float h3 = fmaxf(av.w + bv.w + cv.w, 0.f);
                __nv_bfloat162 hp0; hp0.x = __float2bfloat16(h0); hp0.y = __float2bfloat16(h1);
                __nv_bfloat162 hp1; hp1.x = __float2bfloat16(h2); hp1.y = __float2bfloat16(h3);
                float2 f0 = __bfloat1622float2(hp0);
                float2 f1 = __bfloat1622float2(hp1);
                __nv_bfloat162 lp0 = __floats2bfloat162_rn(h0 - f0.x, h1 - f0.y);
                __nv_bfloat162 lp1 = __floats2bfloat162_rn(h2 - f1.x, h3 - f1.y);
                uint2 hv, lv;
                hv.x = *reinterpret_cast<uint32_t*>(&hp0);
                hv.y = *reinterpret_cast<uint32_t*>(&hp1);
                lv.x = *reinterpret_cast<uint32_t*>(&lp0);
                lv.y = *reinterpret_cast<uint32_t*>(&lp1);
                *(uint2*)(baseHi + u*HSTRIDE_B) = hv;
                *(uint2*)(baseLo + u*HSTRIDE_B) = lv;
            }
        }
        __syncthreads();

        // ---- MMA: warp covers rows [64*mhalf, +64), cols [16*nq, +16) ----
        {
            uint32_t laddrHi = smem_base + A_HI_OFF
                             + (uint32_t)(mhalf*64 + (lane & 15)) * HSTRIDE_B
                             + (uint32_t)(lane >> 4) * 16;
            uint32_t laddrLo = laddrHi + (A_LO_OFF - A_HI_OFF);
#pragma unroll
            for (int mt = 0; mt < 4; mt++) {
                float d[2][4];
#pragma unroll
                for (int ng = 0; ng < 2; ng++)
#pragma unroll
                    for (int x = 0; x < 4; x++) d[ng][x] = 0.f;
                uint32_t mOff = (uint32_t)(mt*16) * HSTRIDE_B;
#pragma unroll
                for (int kt = 0; kt < 8; kt++) {
                    uint32_t aH0,aH1,aH2,aH3, aL0,aL1,aL2,aL3;
                    ldmatrix_x4(aH0,aH1,aH2,aH3, laddrHi + mOff + kt*32);
                    ldmatrix_x4(aL0,aL1,aL2,aL3, laddrLo + mOff + kt*32);
#pragma unroll
                    for (int ng = 0; ng < 2; ng++) {
                        uint32_t h0 = bH[kt][ng*2], h1 = bH[kt][ng*2+1];
                        uint32_t l0 = bL[kt][ng*2], l1 = bL[kt][ng*2+1];
                        mma_bf16(d[ng][0],d[ng][1],d[ng][2],d[ng][3],
                                 aH0,aH1,aH2,aH3, h0, h1);
                        mma_bf16(d[ng][0],d[ng][1],d[ng][2],d[ng][3],
                                 aL0,aL1,aL2,aL3, h0, h1);
                        mma_bf16(d[ng][0],d[ng][1],d[ng][2],d[ng][3],
                                 aH0,aH1,aH2,aH3, l0, l1);
                    }
                }
                // epilogue: rows r0 = 64*mhalf + mt*16 + g, r1 = r0 + 8
                float p0 = fmaf(fmaxf(d[0][0] + b2c[0][0], 0.f), w3c[0][0],
                                fmaxf(d[0][1] + b2c[0][1], 0.f) * w3c[0][1]);
                p0 = fmaf(fmaxf(d[1][0] + b2c[1][0], 0.f), w3c[1][0], p0);
                p0 = fmaf(fmaxf(d[1][1] + b2c[1][1], 0.f), w3c[1][1], p0);
                float p1 = fmaf(fmaxf(d[0][2] + b2c[0][0], 0.f), w3c[0][0],
                                fmaxf(d[0][3] + b2c[0][1], 0.f) * w3c[0][1]);
                p1 = fmaf(fmaxf(d[1][2] + b2c[1][0], 0.f), w3c[1][0], p1);
                p1 = fmaf(fmaxf(d[1][3] + b2c[1][1], 0.f), w3c[1][1], p1);
                p0 += __shfl_xor_sync(0xffffffffu, p0, 1);
                p0 += __shfl_xor_sync(0xffffffffu, p0, 2);
                p1 += __shfl_xor_sync(0xffffffffu, p1, 1);
                p1 += __shfl_xor_sync(0xffffffffu, p1, 2);
                if (t == 0) {
                    int r0 = mhalf*64 + mt*16 + g;
                    red[nq*128 + r0]     = p0;
                    red[nq*128 + r0 + 8] = p1;
                }
            }
        }
        __syncthreads();

        if (tid < 128) {
            int pq = tile*128 + tid;
            if (pq < TOTPAIRS) {
                float s = red[tid] + red[128 + tid] + red[256 + tid] + red[384 + tid];
                g_sim[pq] = tanhf(s + b3s_sh);
            }
        }
        __syncthreads();
    }
}

// ---------------------------------------------------------------------------
// Kernel C (fused seg+final): warp per row r. (unchanged)
// ---------------------------------------------------------------------------
__global__ void final_kernel(const float* __restrict__ users,
                             const float* __restrict__ items,
                             const float* __restrict__ langs,
                             const int* __restrict__ skills,
                             const float* __restrict__ targets,
                             const int* __restrict__ mask,
                             const float* __restrict__ linW,
                             const float* __restrict__ linb,
                             float* __restrict__ out) {
    int r    = (blockIdx.x*blockDim.x + threadIdx.x) >> 5;
    int lane = threadIdx.x & 31;
    if (r >= ROWS) return;
    int n = r / HB, i = r % HB;

    const float* sp = g_sim + n*PP + i*(i-1)/2;
    float s = 0.f;
    for (int k = lane; k < i; k += 32) s += sp[k];

    float acc = 0.f;
    const float* u = users + n*100;
    for (int k = lane; k < 100; k += 32) acc = fmaf(u[k], linW[k], acc);
    const float* it = items + r*100;
    for (int k = lane; k < 100; k += 32) acc = fmaf(it[k], linW[100+k], acc);
    if (lane < 10) acc = fmaf(langs[r*10 + lane], linW[200 + lane], acc);

#pragma unroll
    for (int sh = 16; sh > 0; sh >>= 1) {
        s   += __shfl_xor_sync(0xffffffffu, s,   sh);
        acc += __shfl_xor_sync(0xffffffffu, acc, sh);
    }
    if (lane == 0) {
        int sidx = skills[r];
        float label = targets[r];
        float vt = (sidx != 0) ? s : 0.f;
        float vc = vt * label;
        float logit = acc + linW[210 + sidx]
                    + vt*linW[2210 + sidx]
                    + vc*linW[4210 + sidx]
                    + linb[0];
        float maskf = (mask[r] != 0) ? 1.f : 0.f;
        float bce   = fmaxf(logit, 0.f) - logit*label + log1pf(expf(-fabsf(logit)));
        out[r]          = bce * maskf;
        out[ROWS + r]   = 1.f / (1.f + expf(-logit));
        out[2*ROWS + r] = label;
    }
}

// ---------------------------------------------------------------------------
extern "C" void kernel_launch(void* const* d_in, const int* in_sizes, int n_in,
                              void* d_out, int out_size) {
    const float* users    = (const float*)d_in[0];
    const float* items    = (const float*)d_in[1];
    const float* langs    = (const float*)d_in[2];
    const int*   skills   = (const int*)  d_in[3];
    const float* ts       = (const float*)d_in[4];
    const float* targets  = (const float*)d_in[5];
    const int*   mask     = (const int*)  d_in[6];
    const float* emb      = (const float*)d_in[7];
    const float* W1       = (const float*)d_in[8];
    const float* b1       = (const float*)d_in[9];
    const float* W2       = (const float*)d_in[10];
    const float* b2       = (const float*)d_in[11];
    const float* W3       = (const float*)d_in[12];
    const float* b3       = (const float*)d_in[13];
    const float* linW     = (const float*)d_in[14];
    const float* linb     = (const float*)d_in[15];
    float* out = (float*)d_out;

    size_t prepBytes = (size_t)(2*EMBD*H1D + RPB*EMBD) * sizeof(float);
    static int configured = -1;
    if (configured < 0) {
        cudaFuncSetAttribute(prep_kernel,
                             cudaFuncAttributeMaxDynamicSharedMemorySize,
                             (int)prepBytes);
        cudaFuncSetAttribute(pair_tc_kernel,
                             cudaFuncAttributeMaxDynamicSharedMemorySize,
                             SMEM_DYN);
        configured = 1;
    }

    prep_kernel<<<PREPBLK, PTHREADS, prepBytes>>>(skills, emb, W1, b1);
    pair_tc_kernel<<<TCGRID, 256, SMEM_DYN>>>(skills, ts, W2, b2, W3, b3);
    final_kernel<<<(ROWS*32 + 255)/256, 256>>>(users, items, langs, skills,
                                               targets, mask, linW, linb, out);
}

// round 16
// speedup vs baseline: 5.5411x; 1.2201x over previous
#include <cuda_runtime.h>
#include <cuda_bf16.h>
#include <math.h>
#include <stdint.h>

#define NB 16
#define HB 200
#define EMBD 64
#define H1D 128
#define H1P 129                  // padded row stride for W1 tiles (bank-conflict fix)
#define H2D 64
#define PP 19900                 // H*(H-1)/2
#define ROWS (NB*HB)             // 3200
#define TOTPAIRS (NB*PP)         // 318400
#define W1COLS 134               // 2*EMB + 6

#define RPB 10                   // rows per prep block
#define PREPBLK 320
#define PTHREADS 640             // 20 warps

#define NTILES ((TOTPAIRS + 127) / 128)   // 2488
#define TCGRID 304

#define HSTRIDE_B 272            // h row stride in bytes (128 bf16 + 8 pad)
#define A_HI_OFF 0
#define A_LO_OFF 34816           // 128*272
#define RED_OFF  69632           // + 128*272
#define SMEM_DYN (RED_OFF + 4*128*4)   // 71680

// scratch (device globals; no allocation allowed)
__device__ float g_A[ROWS*H1D];      // e_i @ W1a^T
__device__ float g_B[ROWS*H1D];      // e_j @ W1b^T
__device__ float g_catb[6*H1D];      // W1c[:,cat] + b1
__device__ float g_sim[TOTPAIRS];

__device__ __forceinline__ uint32_t smem_to_u32(const void* p) {
    uint32_t a;
    asm("{ .reg .u64 t; cvta.to.shared.u64 t, %1; cvt.u32.u64 %0, t; }"
        : "=r"(a) : "l"(p));
    return a;
}

__device__ __forceinline__ void ldmatrix_x4(uint32_t& r0, uint32_t& r1,
                                            uint32_t& r2, uint32_t& r3,
                                            uint32_t addr) {
    asm volatile("ldmatrix.sync.aligned.m8n8.x4.shared.b16 {%0,%1,%2,%3}, [%4];"
                 : "=r"(r0), "=r"(r1), "=r"(r2), "=r"(r3) : "r"(addr));
}

__device__ __forceinline__ void mma_bf16(float& d0, float& d1, float& d2, float& d3,
                                         uint32_t a0, uint32_t a1, uint32_t a2, uint32_t a3,
                                         uint32_t b0, uint32_t b1) {
    asm volatile("mma.sync.aligned.m16n8k16.row.col.f32.bf16.bf16.f32 "
                 "{%0,%1,%2,%3}, {%4,%5,%6,%7}, {%8,%9}, {%0,%1,%2,%3};"
                 : "+f"(d0), "+f"(d1), "+f"(d2), "+f"(d3)
                 : "r"(a0), "r"(a1), "r"(a2), "r"(a3), "r"(b0), "r"(b1));
}

// ---------------------------------------------------------------------------
// Kernel A: 320 blocks x 640 threads, 2 blocks/SM. RPB=10 rows per block.
// W1 tiles padded to 129 floats/row: staging STS j*129+c -> bank (j+c)%32,
// conflict-free; compute LDS k*129+c unit-stride, conflict-free.
// ---------------------------------------------------------------------------
__global__ void __launch_bounds__(PTHREADS, 2)
prep_kernel(const int* __restrict__ skills,
            const float* __restrict__ emb,
            const float* __restrict__ W1,
            const float* __restrict__ b1) {
    extern __shared__ float psm[];
    float* W1aT = psm;                 // [k][c] 64x129 (padded)
    float* W1bT = W1aT + EMBD*H1P;     // [k][c] 64x129 (padded)
    float* es   = W1bT + EMBD*H1P;     // [row][k] RPB x 64
    __shared__ int sk[RPB];

    int tid = threadIdx.x;
    int r0  = blockIdx.x * RPB;

    for (int idx = tid; idx < H1D*W1COLS; idx += PTHREADS) {
        int c = idx / W1COLS, j = idx - c*W1COLS;
        float v = W1[idx];
        if (j < EMBD)            W1aT[j*H1P + c] = v;
        else if (j < 2*EMBD)     W1bT[(j-EMBD)*H1P + c] = v;
        else if (blockIdx.x == 0) g_catb[(j-2*EMBD)*H1D + c] = v + b1[c];
    }
    if (tid < RPB) sk[tid] = skills[r0 + tid];
    __syncthreads();
    for (int idx = tid; idx < RPB*EMBD; idx += PTHREADS) {
        int row = idx >> 6, k = idx & 63;
        es[row*EMBD + k] = emb[sk[row]*EMBD + k];
    }
    __syncthreads();

    int c     = tid & 127;
    int rpair = tid >> 7;              // 0..4
    int row0  = rpair*2;
    const float* e0 = es + row0*EMBD;
    const float* e1 = e0 + EMBD;
    float a0 = 0.f, a1 = 0.f, bb0 = 0.f, bb1 = 0.f;
#pragma unroll
    for (int k = 0; k < EMBD; k++) {
        float wa  = W1aT[k*H1P + c];
        float wb  = W1bT[k*H1P + c];
        float ev0 = e0[k], ev1 = e1[k];
        a0  = fmaf(ev0, wa, a0);
        a1  = fmaf(ev1, wa, a1);
        bb0 = fmaf(ev0, wb, bb0);
        bb1 = fmaf(ev1, wb, bb1);
    }
    g_A[(r0+row0  )*H1D + c] = a0;
    g_A[(r0+row0+1)*H1D + c] = a1;
    g_B[(r0+row0  )*H1D + c] = bb0;
    g_B[(r0+row0+1)*H1D + c] = bb1;
}

// ---------------------------------------------------------------------------
// Kernel B: tile = 128 pairs x 64 outputs. (unchanged from R14)
// Warp split: mhalf = wid>>2 (rows 64*mhalf..+63), nq = wid&3 (cols 16*nq..+15).
// ---------------------------------------------------------------------------
__global__ void __launch_bounds__(256, 2)
pair_tc_kernel(const int* __restrict__ skills,
               const float* __restrict__ ts,
               const float* __restrict__ W2,
               const float* __restrict__ b2,
               const float* __restrict__ W3,
               const float* __restrict__ b3) {
    extern __shared__ __align__(16) char smem[];
    float* red = (float*)(smem + RED_OFF);     // [4][128]

    __shared__ float catbs[6*H1D];
    __shared__ float b2s[H2D], W3s[H2D];
    __shared__ float b3s_sh;

    int tid = threadIdx.x, wid = tid >> 5, lane = tid & 31;
    int g = lane >> 2, t = lane & 3;
    int mhalf = wid >> 2;          // 0,1 : rows [64*mhalf, 64*mhalf+64)
    int nq    = wid & 3;           // 0..3: cols [16*nq, 16*nq+16)
    int n0    = nq * 16;

    for (int idx = tid; idx < 6*H1D; idx += 256) catbs[idx] = g_catb[idx];
    if (tid < H2D) { b2s[tid] = b2[tid]; W3s[tid] = W3[tid]; }
    if (tid == 0) b3s_sh = b3[0];

    // ---- W2 hi/lo B-fragments: ng=0 -> col n0+g, ng=1 -> col n0+8+g ----
    uint32_t bH[8][4], bL[8][4];
#pragma unroll
    for (int ng = 0; ng < 2; ng++) {
        const float* wrow = W2 + (n0 + ng*8 + g) * H1D;
#pragma unroll
        for (int kt = 0; kt < 8; kt++) {
#pragma unroll
            for (int hb = 0; hb < 2; hb++) {
                int k0 = kt*16 + t*2 + hb*8;
                float w0 = wrow[k0], w1 = wrow[k0+1];
                __nv_bfloat16 h0 = __float2bfloat16(w0);
                __nv_bfloat16 h1 = __float2bfloat16(w1);
                __nv_bfloat162 hp; hp.x = h0; hp.y = h1;
                __nv_bfloat162 lp = __floats2bfloat162_rn(w0 - __bfloat162float(h0),
                                                          w1 - __bfloat162float(h1));
                bH[kt][ng*2+hb] = *reinterpret_cast<uint32_t*>(&hp);
                bL[kt][ng*2+hb] = *reinterpret_cast<uint32_t*>(&lp);
            }
        }
    }
    __syncthreads();

    uint32_t smem_base = smem_to_u32(smem);
    float b2c[2][2], w3c[2][2];
#pragma unroll
    for (int ng = 0; ng < 2; ng++) {
        b2c[ng][0] = b2s[n0 + ng*8 + t*2];
        b2c[ng][1] = b2s[n0 + ng*8 + t*2 + 1];
        w3c[ng][0] = W3s[n0 + ng*8 + t*2];
        w3c[ng][1] = W3s[n0 + ng*8 + t*2 + 1];
    }

    for (int tile = blockIdx.x; tile < NTILES; tile += TCGRID) {
        // ---- phase 1: per-lane pair indices for u = lane&15, then broadcast ----
        int ri_l, rj_l, cat_l;
        {
            int u_l = lane & 15;
            int pq = tile*128 + wid*16 + u_l;
            int q  = (pq < TOTPAIRS) ? pq : (TOTPAIRS - 1);
            int n  = q / PP, p = q - n*PP;
            int i = (int)((1.0f + sqrtf(1.0f + 8.0f*(float)p)) * 0.5f);
            while (i*(i-1)/2 > p)  --i;
            while ((i+1)*i/2 <= p) ++i;
            int j = p - i*(i-1)/2;
            ri_l = n*HB + i;
            rj_l = n*HB + j;
            float dt = ts[ri_l] - ts[rj_l];
            cat_l = 1 + (dt > 1.f) + (dt > 3600.f) + (dt > 86400.f) + (dt > 604800.f);
            if (skills[ri_l] == 0 || skills[rj_l] == 0) cat_l = 0;
        }
        {
            int c0 = lane * 4;
            char* baseHi = smem + A_HI_OFF + (wid*16)*HSTRIDE_B + c0*2;
            char* baseLo = smem + A_LO_OFF + (wid*16)*HSTRIDE_B + c0*2;
#pragma unroll 4
            for (int u = 0; u < 16; u++) {
                int ri  = __shfl_sync(0xffffffffu, ri_l, u);
                int rj  = __shfl_sync(0xffffffffu, rj_l, u);
                int cat = __shfl_sync(0xffffffffu, cat_l, u);
                float4 av = *(const float4*)(g_A + ri*H1D + c0);
                float4 bv = *(const float4*)(g_B + rj*H1D + c0);
                float4 cv = *(const float4*)(catbs + cat*H1D + c0);
                float h0 = fmaxf(av.x + bv.x + cv.x, 0.f);
                float h1 = fmaxf(av.y + bv.y + cv.y, 0.f);
                float h2 = fmaxf(av.z + bv.z + cv.z, 0.f);
                float h3 = fmaxf(av.w + bv.w + cv.w, 0.f);
                __nv_bfloat162 hp0; hp0.x = __float2bfloat16(h0); hp0.y = __float2bfloat16(h1);
                __nv_bfloat162 hp1; hp1.x = __float2bfloat16(h2); hp1.y = __float2bfloat16(h3);
                float2 f0 = __bfloat1622float2(hp0);
                float2 f1 = __bfloat1622float2(hp1);
                __nv_bfloat162 lp0 = __floats2bfloat162_rn(h0 - f0.x, h1 - f0.y);
                __nv_bfloat162 lp1 = __floats2bfloat162_rn(h2 - f1.x, h3 - f1.y);
                uint2 hv, lv;
                hv.x = *reinterpret_cast<uint32_t*>(&hp0);
                hv.y = *reinterpret_cast<uint32_t*>(&hp1);
                lv.x = *reinterpret_cast<uint32_t*>(&lp0);
                lv.y = *reinterpret_cast<uint32_t*>(&lp1);
                *(uint2*)(baseHi + u*HSTRIDE_B) = hv;
                *(uint2*)(baseLo + u*HSTRIDE_B) = lv;
            }
        }
        __syncthreads();

        // ---- MMA: warp covers rows [64*mhalf, +64), cols [16*nq, +16) ----
        {
            uint32_t laddrHi = smem_base + A_HI_OFF
                             + (uint32_t)(mhalf*64 + (lane & 15)) * HSTRIDE_B
                             + (uint32_t)(lane >> 4) * 16;
            uint32_t laddrLo = laddrHi + (A_LO_OFF - A_HI_OFF);
#pragma unroll
            for (int mt = 0; mt < 4; mt++) {
                float d[2][4];
#pragma unroll
                for (int ng = 0; ng < 2; ng++)
#pragma unroll
                    for (int x = 0; x < 4; x++) d[ng][x] = 0.f;
                uint32_t mOff = (uint32_t)(mt*16) * HSTRIDE_B;
#pragma unroll
                for (int kt = 0; kt < 8; kt++) {
                    uint32_t aH0,aH1,aH2,aH3, aL0,aL1,aL2,aL3;
                    ldmatrix_x4(aH0,aH1,aH2,aH3, laddrHi + mOff + kt*32);
                    ldmatrix_x4(aL0,aL1,aL2,aL3, laddrLo + mOff + kt*32);
#pragma unroll
                    for (int ng = 0; ng < 2; ng++) {
                        uint32_t h0 = bH[kt][ng*2], h1 = bH[kt][ng*2+1];
                        uint32_t l0 = bL[kt][ng*2], l1 = bL[kt][ng*2+1];
                        mma_bf16(d[ng][0],d[ng][1],d[ng][2],d[ng][3],
                                 aH0,aH1,aH2,aH3, h0, h1);
                        mma_bf16(d[ng][0],d[ng][1],d[ng][2],d[ng][3],
                                 aL0,aL1,aL2,aL3, h0, h1);
                        mma_bf16(d[ng][0],d[ng][1],d[ng][2],d[ng][3],
                                 aH0,aH1,aH2,aH3, l0, l1);
                    }
                }
                float p0 = fmaf(fmaxf(d[0][0] + b2c[0][0], 0.f), w3c[0][0],
                                fmaxf(d[0][1] + b2c[0][1], 0.f) * w3c[0][1]);
                p0 = fmaf(fmaxf(d[1][0] + b2c[1][0], 0.f), w3c[1][0], p0);
                p0 = fmaf(fmaxf(d[1][1] + b2c[1][1], 0.f), w3c[1][1], p0);
                float p1 = fmaf(fmaxf(d[0][2] + b2c[0][0], 0.f), w3c[0][0],
                                fmaxf(d[0][3] + b2c[0][1], 0.f) * w3c[0][1]);
                p1 = fmaf(fmaxf(d[1][2] + b2c[1][0], 0.f), w3c[1][0], p1);
                p1 = fmaf(fmaxf(d[1][3] + b2c[1][1], 0.f), w3c[1][1], p1);
                p0 += __shfl_xor_sync(0xffffffffu, p0, 1);
                p0 += __shfl_xor_sync(0xffffffffu, p0, 2);
                p1 += __shfl_xor_sync(0xffffffffu, p1, 1);
                p1 += __shfl_xor_sync(0xffffffffu, p1, 2);
                if (t == 0) {
                    int r0 = mhalf*64 + mt*16 + g;
                    red[nq*128 + r0]     = p0;
                    red[nq*128 + r0 + 8] = p1;
                }
            }
        }
        __syncthreads();

        if (tid < 128) {
            int pq = tile*128 + tid;
            if (pq < TOTPAIRS) {
                float s = red[tid] + red[128 + tid] + red[256 + tid] + red[384 + tid];
                g_sim[pq] = tanhf(s + b3s_sh);
            }
        }
        __syncthreads();
    }
}

// ---------------------------------------------------------------------------
// Kernel C (fused seg+final): warp per row r. (unchanged)
// ---------------------------------------------------------------------------
__global__ void final_kernel(const float* __restrict__ users,
                             const float* __restrict__ items,
                             const float* __restrict__ langs,
                             const int* __restrict__ skills,
                             const float* __restrict__ targets,
                             const int* __restrict__ mask,
                             const float* __restrict__ linW,
                             const float* __restrict__ linb,
                             float* __restrict__ out) {
    int r    = (blockIdx.x*blockDim.x + threadIdx.x) >> 5;
    int lane = threadIdx.x & 31;
    if (r >= ROWS) return;
    int n = r / HB, i = r % HB;

    const float* sp = g_sim + n*PP + i*(i-1)/2;
    float s = 0.f;
    for (int k = lane; k < i; k += 32) s += sp[k];

    float acc = 0.f;
    const float* u = users + n*100;
    for (int k = lane; k < 100; k += 32) acc = fmaf(u[k], linW[k], acc);
    const float* it = items + r*100;
    for (int k = lane; k < 100; k += 32) acc = fmaf(it[k], linW[100+k], acc);
    if (lane < 10) acc = fmaf(langs[r*10 + lane], linW[200 + lane], acc);

#pragma unroll
    for (int sh = 16; sh > 0; sh >>= 1) {
        s   += __shfl_xor_sync(0xffffffffu, s,   sh);
        acc += __shfl_xor_sync(0xffffffffu, acc, sh);
    }
    if (lane == 0) {
        int sidx = skills[r];
        float label = targets[r];
        float vt = (sidx != 0) ? s : 0.f;
        float vc = vt * label;
        float logit = acc + linW[210 + sidx]
                    + vt*linW[2210 + sidx]
                    + vc*linW[4210 + sidx]
                    + linb[0];
        float maskf = (mask[r] != 0) ? 1.f : 0.f;
        float bce   = fmaxf(logit, 0.f) - logit*label + log1pf(expf(-fabsf(logit)));
        out[r]          = bce * maskf;
        out[ROWS + r]   = 1.f / (1.f + expf(-logit));
        out[2*ROWS + r] = label;
    }
}

// ---------------------------------------------------------------------------
extern "C" void kernel_launch(void* const* d_in, const int* in_sizes, int n_in,
                              void* d_out, int out_size) {
    const float* users    = (const float*)d_in[0];
    const float* items    = (const float*)d_in[1];
    const float* langs    = (const float*)d_in[2];
    const int*   skills   = (const int*)  d_in[3];
    const float* ts       = (const float*)d_in[4];
    const float* targets  = (const float*)d_in[5];
    const int*   mask     = (const int*)  d_in[6];
    const float* emb      = (const float*)d_in[7];
    const float* W1       = (const float*)d_in[8];
    const float* b1       = (const float*)d_in[9];
    const float* W2       = (const float*)d_in[10];
    const float* b2       = (const float*)d_in[11];
    const float* W3       = (const float*)d_in[12];
    const float* b3       = (const float*)d_in[13];
    const float* linW     = (const float*)d_in[14];
    const float* linb     = (const float*)d_in[15];
    float* out = (float*)d_out;

    size_t prepBytes = (size_t)(2*EMBD*H1P + RPB*EMBD) * sizeof(float);
    static int configured = -1;
    if (configured < 0) {
        cudaFuncSetAttribute(prep_kernel,
                             cudaFuncAttributeMaxDynamicSharedMemorySize,
                             (int)prepBytes);
        cudaFuncSetAttribute(pair_tc_kernel,
                             cudaFuncAttributeMaxDynamicSharedMemorySize,
                             SMEM_DYN);
        configured = 1;
    }

    prep_kernel<<<PREPBLK, PTHREADS, prepBytes>>>(skills, emb, W1, b1);
    pair_tc_kernel<<<TCGRID, 256, SMEM_DYN>>>(skills, ts, W2, b2, W3, b3);
    final_kernel<<<(ROWS*32 + 255)/256, 256>>>(users, items, langs, skills,
                                               targets, mask, linW, linb, out);
}